// round 1
// baseline (speedup 1.0000x reference)
#include <cuda_runtime.h>
#include <math.h>

#define BB 256
#define TIN 49
#define TOUT 25
#define NB 24
#define HH 128
#define FIVEH 640
#define KTOT 384

// ---------------- device scratch (no allocations allowed) ----------------
__device__ float g_Wcat[2 * NB * KTOT * FIVEH];   // [l][j][k][n], tf32-rounded, 94.4MB
__device__ float g_h0[TOUT * NB * BB * HH];       // layer-0 h, [t][j][b][h]
__device__ float g_c0[TOUT * NB * BB * HH];       // layer-0 c
__device__ float g_rowh[2 * NB * BB * HH];        // [l][j][b][h] initial temporal h
__device__ float g_rowc[NB * BB * HH];            // [j][b][h]   initial temporal c
__device__ float g_colh[BB * HH];                 // [b][h]      initial spatial h
__device__ float g_colc[BB * HH];                 // [b][h]      initial spatial c
__device__ unsigned long long g_bar;              // grid barrier counter

// ---------------- helpers ----------------
__device__ __forceinline__ float sigm(float x) { return 1.0f / (1.0f + __expf(-x)); }
__device__ __forceinline__ float tanh_fast(float x) { return 2.0f / (1.0f + __expf(-2.0f * x)) - 1.0f; }

__device__ __forceinline__ unsigned f2tf32(float v) {
    unsigned u;
    asm("cvt.rna.tf32.f32 %0, %1;" : "=r"(u) : "f"(v));
    return u;
}

__device__ __forceinline__ void mma_tf32(float* c, const unsigned* a, unsigned b0, unsigned b1) {
    asm volatile(
        "mma.sync.aligned.m16n8k8.row.col.f32.tf32.tf32.f32 "
        "{%0,%1,%2,%3}, {%4,%5,%6,%7}, {%8,%9}, {%0,%1,%2,%3};\n"
        : "+f"(c[0]), "+f"(c[1]), "+f"(c[2]), "+f"(c[3])
        : "r"(a[0]), "r"(a[1]), "r"(a[2]), "r"(a[3]), "r"(b0), "r"(b1));
}

// ---------------- prep kernels ----------------
// Pack U|Wt|Ws into g_Wcat[l][j][k(0..383)][n], rounded to tf32. Also reset barrier.
__global__ void prep_weights(const float* __restrict__ U, const float* __restrict__ Wt,
                             const float* __restrict__ Ws) {
    const int total = 2 * NB * KTOT * FIVEH;
    for (int i = blockIdx.x * blockDim.x + threadIdx.x; i < total; i += gridDim.x * blockDim.x) {
        int n = i % FIVEH;
        int r = i / FIVEH;
        int k = r % KTOT;
        int lj = r / KTOT;  // l*NB + j
        const float* src;
        int kk = k;
        if (k < HH) { src = U; }
        else if (k < 2 * HH) { src = Wt; kk = k - HH; }
        else { src = Ws; kk = k - 2 * HH; }
        float v = src[(lj * HH + kk) * FIVEH + n];
        g_Wcat[i] = __uint_as_float(f2tf32(v));
    }
    if (blockIdx.x == 0 && threadIdx.x == 0) g_bar = 0ULL;
}

// Row means over TIN: g_rowh[0/1], g_rowc. One thread per (j,b,h).
__global__ void prep_rows(const float* __restrict__ hs, const float* __restrict__ cs,
                          const float* __restrict__ gts) {
    int i = blockIdx.x * blockDim.x + threadIdx.x;
    const int total = NB * BB * HH;
    if (i >= total) return;
    int h = i % HH;
    int b = (i / HH) % BB;
    int j = i / (HH * BB);
    const float* ph = hs + (b * TIN * NB + j) * HH + h;
    const float* pc = cs + (b * TIN * NB + j) * HH + h;
    float sh = 0.f, sc = 0.f;
    for (int t = 0; t < TIN; t++) { sh += ph[t * NB * HH]; sc += pc[t * NB * HH]; }
    float gv = gts[(b * NB + j) * HH + h];
    g_rowh[(0 * NB + j) * BB * HH + b * HH + h] = sh / 49.0f;
    g_rowh[(1 * NB + j) * BB * HH + b * HH + h] = (sh + gv) / 50.0f;
    g_rowc[j * BB * HH + b * HH + h] = sc / 49.0f;
}

// Col means over NB of the row means (== mean over (TIN,NB)).
__global__ void prep_cols() {
    int i = blockIdx.x * blockDim.x + threadIdx.x;  // (b,h)
    if (i >= BB * HH) return;
    float sh = 0.f, sc = 0.f;
    for (int j = 0; j < NB; j++) {
        sh += g_rowh[j * BB * HH + i];
        sc += g_rowc[j * BB * HH + i];
    }
    g_colh[i] = sh / (float)NB;
    g_colc[i] = sc / (float)NB;
}

// ---------------- main persistent kernel ----------------
// CTA tile: M=128 (batch), N=160 = 5 gates x 32 h-columns, K=384 streamed in 12 chunks of 32.
// 256 threads = 8 warps as 4(M) x 2(N); warp tile 32x80, acc 80 fp32/thread.
// Smem: As[128][36] (tf32 bits) + Bs[32][168] overlap with Zs[128][161] (fp32 z tile).

#define AS_STRIDE 36
#define BS_STRIDE 168
#define ZS_STRIDE 161
#define SMEM_BYTES (128 * ZS_STRIDE * 4)  // 82432 (> As+Bs = 39936)

__device__ void process_cell_tile(int t, int j, int l, int mtile, int htile,
                                  const float* __restrict__ p, const float* __restrict__ bias,
                                  float* __restrict__ outh, float* __restrict__ outc,
                                  char* smem_raw) {
    unsigned* AsU = (unsigned*)smem_raw;            // [128][36]
    unsigned* BsU = AsU + 128 * AS_STRIDE;          // [32][168]
    float* Zs = (float*)smem_raw;                   // [128][161] (overlaps, sync-guarded)

    const int tid = threadIdx.x;
    const int warp = tid >> 5, lane = tid & 31;
    const int wm = warp >> 1, wn = warp & 1;
    const int g = lane >> 2, tg = lane & 3;
    const int b0 = mtile << 7;   // batch offset
    const int h0 = htile << 5;   // h offset

    // ---- A operand sources: k 0..127 = x, 128..255 = h_t, 256..383 = h_s ----
    const float* srcs[3];
    int strides[3];
    if (l == 0) { srcs[0] = p + ((b0 * TOUT + t) * NB + j) * HH; strides[0] = TOUT * NB * HH; }
    else        { srcs[0] = g_h0 + ((t * NB + j) * BB + b0) * HH; strides[0] = HH; }

    if (t == 0)      { srcs[1] = g_rowh + ((l * NB + j) * BB + b0) * HH; strides[1] = HH; }
    else if (l == 0) { srcs[1] = g_h0 + (((t - 1) * NB + j) * BB + b0) * HH; strides[1] = HH; }
    else             { srcs[1] = outh + ((b0 * TOUT + (t - 1)) * NB + j) * HH; strides[1] = TOUT * NB * HH; }

    if (j == 0)      { srcs[2] = g_colh + b0 * HH; strides[2] = HH; }
    else if (l == 0) { srcs[2] = g_h0 + ((t * NB + (j - 1)) * BB + b0) * HH; strides[2] = HH; }
    else             { srcs[2] = outh + ((b0 * TOUT + t) * NB + (j - 1)) * HH; strides[2] = TOUT * NB * HH; }

    const float* Wb = g_Wcat + (l * NB + j) * (KTOT * FIVEH);

    float acc[2][10][4];
#pragma unroll
    for (int i = 0; i < 2; i++)
#pragma unroll
        for (int f = 0; f < 10; f++)
#pragma unroll
            for (int ci = 0; ci < 4; ci++) acc[i][f][ci] = 0.0f;

    for (int kc = 0; kc < 12; kc++) {
        const float* asrc = srcs[kc >> 2];
        const int astr = strides[kc >> 2];
        const int hoff = (kc & 3) << 5;
        __syncthreads();
        // A tile 128x32 -> tf32 -> smem. 1024 float4.
#pragma unroll
        for (int i = 0; i < 4; i++) {
            int idx = tid + (i << 8);
            int r = idx >> 3;
            int c4 = (idx & 7) << 2;
            float4 v = *(const float4*)(asrc + r * astr + hoff + c4);
            uint4 u;
            u.x = f2tf32(v.x); u.y = f2tf32(v.y); u.z = f2tf32(v.z); u.w = f2tf32(v.w);
            *(uint4*)(AsU + r * AS_STRIDE + c4) = u;
        }
        // B tile 32x160 (cols c = gate*32+hh -> W col n = gate*128 + h0 + hh). 1280 float4.
        const float* wsrc = Wb + (kc << 5) * FIVEH;
#pragma unroll
        for (int i = 0; i < 5; i++) {
            int idx = tid + (i << 8);
            int k = idx / 40;
            int cc = (idx % 40) << 2;
            int n = ((cc >> 5) << 7) + h0 + (cc & 31);
            float4 v = *(const float4*)(wsrc + k * FIVEH + n);
            *(float4*)((float*)BsU + k * BS_STRIDE + cc) = v;
        }
        __syncthreads();
#pragma unroll
        for (int ks = 0; ks < 4; ks++) {
            const int kk = ks << 3;
            unsigned a[2][4];
#pragma unroll
            for (int mi = 0; mi < 2; mi++) {
                int row = (wm << 5) + (mi << 4);
                a[mi][0] = AsU[(row + g) * AS_STRIDE + kk + tg];
                a[mi][1] = AsU[(row + g + 8) * AS_STRIDE + kk + tg];
                a[mi][2] = AsU[(row + g) * AS_STRIDE + kk + tg + 4];
                a[mi][3] = AsU[(row + g + 8) * AS_STRIDE + kk + tg + 4];
            }
#pragma unroll
            for (int f = 0; f < 10; f++) {
                int c = wn * 80 + (f << 3) + g;
                unsigned bb0 = BsU[(kk + tg) * BS_STRIDE + c];
                unsigned bb1 = BsU[(kk + tg + 4) * BS_STRIDE + c];
                mma_tf32(acc[0][f], a[0], bb0, bb1);
                mma_tf32(acc[1][f], a[1], bb0, bb1);
            }
        }
    }
    __syncthreads();
    // stage z to smem (fp32)
#pragma unroll
    for (int mi = 0; mi < 2; mi++)
#pragma unroll
        for (int f = 0; f < 10; f++) {
            int rb = (wm << 5) + (mi << 4) + g;
            int cb = wn * 80 + (f << 3) + (tg << 1);
            Zs[rb * ZS_STRIDE + cb] = acc[mi][f][0];
            Zs[rb * ZS_STRIDE + cb + 1] = acc[mi][f][1];
            Zs[(rb + 8) * ZS_STRIDE + cb] = acc[mi][f][2];
            Zs[(rb + 8) * ZS_STRIDE + cb + 1] = acc[mi][f][3];
        }
    __syncthreads();

    // ---- elementwise gate fusion ----
    const float* brow = bias + (l * NB + j) * FIVEH;
    const float* ctp; int cts;
    if (t == 0)      { ctp = g_rowc + (j * BB + b0) * HH; cts = HH; }
    else if (l == 0) { ctp = g_c0 + (((t - 1) * NB + j) * BB + b0) * HH; cts = HH; }
    else             { ctp = outc + ((b0 * TOUT + (t - 1)) * NB + j) * HH; cts = TOUT * NB * HH; }
    const float* csp; int css;
    if (j == 0)      { csp = g_colc + b0 * HH; css = HH; }
    else if (l == 0) { csp = g_c0 + ((t * NB + (j - 1)) * BB + b0) * HH; css = HH; }
    else             { csp = outc + ((b0 * TOUT + t) * NB + (j - 1)) * HH; css = TOUT * NB * HH; }

    float *oh, *oc; int os;
    if (l == 0) {
        oh = g_h0 + ((t * NB + j) * BB + b0) * HH;
        oc = g_c0 + ((t * NB + j) * BB + b0) * HH;
        os = HH;
    } else {
        oh = outh + ((b0 * TOUT + t) * NB + j) * HH;
        oc = outc + ((b0 * TOUT + t) * NB + j) * HH;
        os = TOUT * NB * HH;
    }

    for (int e = tid; e < 128 * 32; e += 256) {
        int m = e >> 5, hh = e & 31;
        int ha = h0 + hh;
        // gate order: i, f_s, f_t, o, g
        float zi = Zs[m * ZS_STRIDE + hh] + brow[ha];
        float zfs = Zs[m * ZS_STRIDE + 32 + hh] + brow[128 + ha];
        float zft = Zs[m * ZS_STRIDE + 64 + hh] + brow[256 + ha];
        float zo = Zs[m * ZS_STRIDE + 96 + hh] + brow[384 + ha];
        float zg = Zs[m * ZS_STRIDE + 128 + hh] + brow[512 + ha];
        float ctv = ctp[m * cts + ha];
        float csv = csp[m * css + ha];
        float cv = sigm(zi) * tanh_fast(zg) + sigm(zft) * ctv + sigm(zfs) * csv;
        float hv = sigm(zo) * tanh_fast(cv);
        oh[m * os + ha] = hv;
        oc[m * os + ha] = cv;
    }
}

__global__ void __launch_bounds__(256)
st_main(const float* __restrict__ p, const float* __restrict__ bias,
        float* __restrict__ outh, float* __restrict__ outc) {
    extern __shared__ char smem_raw[];
    unsigned long long gen = 0;
    for (int s = 0; s < TOUT + NB - 1; s++) {
        int t_lo = (s - (NB - 1) > 0) ? s - (NB - 1) : 0;
        int t_hi = (s < TOUT - 1) ? s : TOUT - 1;
        int nitems = (t_hi - t_lo + 1) << 3;  // 8 tiles/cell
        for (int l = 0; l < 2; l++) {
            for (int it = blockIdx.x; it < nitems; it += gridDim.x) {
                int t = t_lo + (it >> 3);
                int jj = s - t;
                process_cell_tile(t, jj, l, (it >> 2) & 1, it & 3, p, bias, outh, outc, smem_raw);
            }
            // grid barrier (monotonic counter; reset each launch by prep_weights)
            gen++;
            __syncthreads();
            if (threadIdx.x == 0) {
                __threadfence();
                atomicAdd(&g_bar, 1ULL);
                unsigned long long target = gen * (unsigned long long)gridDim.x;
                while (*(volatile unsigned long long*)&g_bar < target) __nanosleep(64);
                __threadfence();
            }
            __syncthreads();
        }
    }
}

// ---------------- launch ----------------
extern "C" void kernel_launch(void* const* d_in, const int* in_sizes, int n_in,
                              void* d_out, int out_size) {
    const float* hs = (const float*)d_in[0];   // hidden_states [B,TIN,NB,H]
    const float* cs = (const float*)d_in[1];   // cell_states
    const float* gts = (const float*)d_in[2];  // global_t_state [B,NB,H]
    const float* p = (const float*)d_in[3];    // p [B,TOUT,NB,H]
    const float* U = (const float*)d_in[4];
    const float* Wt = (const float*)d_in[5];
    const float* Ws = (const float*)d_in[6];
    const float* b = (const float*)d_in[7];

    float* outh = (float*)d_out;
    float* outc = outh + (size_t)BB * TOUT * NB * HH;

    prep_weights<<<2048, 256>>>(U, Wt, Ws);
    prep_rows<<<(NB * BB * HH + 255) / 256, 256>>>(hs, cs, gts);
    prep_cols<<<(BB * HH + 255) / 256, 256>>>();

    int dev = 0;
    cudaGetDevice(&dev);
    int nsm = 148;
    cudaDeviceGetAttribute(&nsm, cudaDevAttrMultiProcessorCount, dev);
    cudaFuncSetAttribute(st_main, cudaFuncAttributeMaxDynamicSharedMemorySize, SMEM_BYTES);
    int occ = 1;
    cudaOccupancyMaxActiveBlocksPerMultiprocessor(&occ, st_main, 256, SMEM_BYTES);
    if (occ < 1) occ = 1;
    st_main<<<nsm * occ, 256, SMEM_BYTES>>>(p, b, outh, outc);
}

// round 2
// speedup vs baseline: 1.3057x; 1.3057x over previous
#include <cuda_runtime.h>
#include <math.h>

#define BB 256
#define TIN 49
#define TOUT 25
#define NB 24
#define HH 128
#define FIVEH 640
#define KTOT 384

// ---------------- device scratch (no allocations allowed) ----------------
__device__ float g_Wcat[2 * NB * KTOT * FIVEH];   // [l][j][k][n], tf32-rounded
__device__ float g_h0[TOUT * NB * BB * HH];       // layer-0 h, [t][j][b][h]
__device__ float g_c0[TOUT * NB * BB * HH];       // layer-0 c
__device__ float g_rowh[2 * NB * BB * HH];        // [l][j][b][h] initial temporal h
__device__ float g_rowc[NB * BB * HH];            // [j][b][h]   initial temporal c
__device__ float g_colh[BB * HH];                 // [b][h]      initial spatial h
__device__ float g_colc[BB * HH];                 // [b][h]      initial spatial c
__device__ unsigned long long g_bar;              // grid barrier counter

// ---------------- helpers ----------------
__device__ __forceinline__ float sigm(float x) { return 1.0f / (1.0f + __expf(-x)); }
__device__ __forceinline__ float tanh_fast(float x) { return 2.0f / (1.0f + __expf(-2.0f * x)) - 1.0f; }

__device__ __forceinline__ unsigned f2tf32(float v) {
    unsigned u;
    asm("cvt.rna.tf32.f32 %0, %1;" : "=r"(u) : "f"(v));
    return u;
}

__device__ __forceinline__ void mma_tf32(float* c, const unsigned* a, unsigned b0, unsigned b1) {
    asm volatile(
        "mma.sync.aligned.m16n8k8.row.col.f32.tf32.tf32.f32 "
        "{%0,%1,%2,%3}, {%4,%5,%6,%7}, {%8,%9}, {%0,%1,%2,%3};\n"
        : "+f"(c[0]), "+f"(c[1]), "+f"(c[2]), "+f"(c[3])
        : "r"(a[0]), "r"(a[1]), "r"(a[2]), "r"(a[3]), "r"(b0), "r"(b1));
}

__device__ __forceinline__ void cp16(float* dst_smem, const float* src_gmem) {
    unsigned d = (unsigned)__cvta_generic_to_shared(dst_smem);
    asm volatile("cp.async.cg.shared.global [%0], [%1], 16;\n" ::"r"(d), "l"(src_gmem));
}
__device__ __forceinline__ void cp_commit() { asm volatile("cp.async.commit_group;\n"); }
template <int N>
__device__ __forceinline__ void cp_wait() { asm volatile("cp.async.wait_group %0;\n" ::"n"(N)); }

// ---------------- prep kernels ----------------
__global__ void prep_weights(const float* __restrict__ U, const float* __restrict__ Wt,
                             const float* __restrict__ Ws) {
    const int total = 2 * NB * KTOT * FIVEH;
    for (int i = blockIdx.x * blockDim.x + threadIdx.x; i < total; i += gridDim.x * blockDim.x) {
        int n = i % FIVEH;
        int r = i / FIVEH;
        int k = r % KTOT;
        int lj = r / KTOT;
        const float* src;
        int kk = k;
        if (k < HH) { src = U; }
        else if (k < 2 * HH) { src = Wt; kk = k - HH; }
        else { src = Ws; kk = k - 2 * HH; }
        float v = src[(lj * HH + kk) * FIVEH + n];
        g_Wcat[i] = __uint_as_float(f2tf32(v));
    }
    if (blockIdx.x == 0 && threadIdx.x == 0) g_bar = 0ULL;
}

__global__ void prep_rows(const float* __restrict__ hs, const float* __restrict__ cs,
                          const float* __restrict__ gts) {
    int i = blockIdx.x * blockDim.x + threadIdx.x;
    const int total = NB * BB * HH;
    if (i >= total) return;
    int h = i % HH;
    int b = (i / HH) % BB;
    int j = i / (HH * BB);
    const float* ph = hs + (b * TIN * NB + j) * HH + h;
    const float* pc = cs + (b * TIN * NB + j) * HH + h;
    float sh = 0.f, sc = 0.f;
    for (int t = 0; t < TIN; t++) { sh += ph[t * NB * HH]; sc += pc[t * NB * HH]; }
    float gv = gts[(b * NB + j) * HH + h];
    g_rowh[(0 * NB + j) * BB * HH + b * HH + h] = sh / 49.0f;
    g_rowh[(1 * NB + j) * BB * HH + b * HH + h] = (sh + gv) / 50.0f;
    g_rowc[j * BB * HH + b * HH + h] = sc / 49.0f;
}

__global__ void prep_cols() {
    int i = blockIdx.x * blockDim.x + threadIdx.x;
    if (i >= BB * HH) return;
    float sh = 0.f, sc = 0.f;
    for (int j = 0; j < NB; j++) {
        sh += g_rowh[j * BB * HH + i];
        sc += g_rowc[j * BB * HH + i];
    }
    g_colh[i] = sh / (float)NB;
    g_colc[i] = sc / (float)NB;
}

// ---------------- main persistent kernel ----------------
// CTA tile: M=128 (batch), N=160 = 5 gates x 32 h-cols, K=384 in 12 chunks of 32.
// 3-stage cp.async pipeline. A stored as raw fp32 in smem, tf32-rounded at consume
// (numerically identical to rounding before store).

#define AS_STRIDE 36
#define BS_STRIDE 168
#define ZS_STRIDE 161
#define A_STAGE (128 * AS_STRIDE)
#define B_STAGE (32 * BS_STRIDE)
#define STAGE_FLOATS (A_STAGE + B_STAGE)   // 9984 floats = 39936 B
#define STAGES 3
#define SMEM_BYTES (STAGES * STAGE_FLOATS * 4)  // 119808 B (Z tile 82432 B overlaps)

__device__ __forceinline__ void issue_chunk(const float* __restrict__ asrc, int astr, int hoff,
                                            const float* __restrict__ wsrc, int h0,
                                            float* stage) {
    float* As = stage;
    float* Bs = stage + A_STAGE;
    const int tid = threadIdx.x;
#pragma unroll
    for (int i = 0; i < 4; i++) {
        int idx = tid + (i << 8);
        int r = idx >> 3;
        int c4 = (idx & 7) << 2;
        cp16(As + r * AS_STRIDE + c4, asrc + r * astr + hoff + c4);
    }
#pragma unroll
    for (int i = 0; i < 5; i++) {
        int idx = tid + (i << 8);
        int k = idx / 40;
        int cc = (idx % 40) << 2;
        int n = ((cc >> 5) << 7) + h0 + (cc & 31);
        cp16(Bs + k * BS_STRIDE + cc, wsrc + k * FIVEH + n);
    }
}

__device__ void process_cell_tile(int t, int j, int l, int mtile, int htile,
                                  const float* __restrict__ p, const float* __restrict__ bias,
                                  float* __restrict__ outh, float* __restrict__ outc,
                                  char* smem_raw) {
    float* smem = (float*)smem_raw;
    float* Zs = smem;  // [128][161] fp32, overlaps stage buffers (sync-guarded)

    const int tid = threadIdx.x;
    const int warp = tid >> 5, lane = tid & 31;
    const int wm = warp >> 1, wn = warp & 1;
    const int g = lane >> 2, tg = lane & 3;
    const int b0 = mtile << 7;
    const int h0 = htile << 5;

    // ---- A operand sources: k 0..127 = x, 128..255 = h_t, 256..383 = h_s ----
    const float* srcs[3];
    int strides[3];
    if (l == 0) { srcs[0] = p + ((b0 * TOUT + t) * NB + j) * HH; strides[0] = TOUT * NB * HH; }
    else        { srcs[0] = g_h0 + ((t * NB + j) * BB + b0) * HH; strides[0] = HH; }

    if (t == 0)      { srcs[1] = g_rowh + ((l * NB + j) * BB + b0) * HH; strides[1] = HH; }
    else if (l == 0) { srcs[1] = g_h0 + (((t - 1) * NB + j) * BB + b0) * HH; strides[1] = HH; }
    else             { srcs[1] = outh + ((b0 * TOUT + (t - 1)) * NB + j) * HH; strides[1] = TOUT * NB * HH; }

    if (j == 0)      { srcs[2] = g_colh + b0 * HH; strides[2] = HH; }
    else if (l == 0) { srcs[2] = g_h0 + ((t * NB + (j - 1)) * BB + b0) * HH; strides[2] = HH; }
    else             { srcs[2] = outh + ((b0 * TOUT + t) * NB + (j - 1)) * HH; strides[2] = TOUT * NB * HH; }

    const float* Wb = g_Wcat + (l * NB + j) * (KTOT * FIVEH);

    float acc[2][10][4];
#pragma unroll
    for (int i = 0; i < 2; i++)
#pragma unroll
        for (int f = 0; f < 10; f++)
#pragma unroll
            for (int ci = 0; ci < 4; ci++) acc[i][f][ci] = 0.0f;

    __syncthreads();  // previous tile's Z region fully consumed before stage copies

    // prologue: issue chunks 0..STAGES-2
#pragma unroll
    for (int s = 0; s < STAGES - 1; s++) {
        issue_chunk(srcs[s >> 2], strides[s >> 2], (s & 3) << 5,
                    Wb + (s << 5) * FIVEH, h0, smem + s * STAGE_FLOATS);
        cp_commit();
    }

    for (int kc = 0; kc < 12; kc++) {
        cp_wait<STAGES - 2>();
        __syncthreads();
        int nxt = kc + STAGES - 1;
        if (nxt < 12) {
            issue_chunk(srcs[nxt >> 2], strides[nxt >> 2], (nxt & 3) << 5,
                        Wb + (nxt << 5) * FIVEH, h0, smem + (nxt % STAGES) * STAGE_FLOATS);
        }
        cp_commit();

        const float* As = smem + (kc % STAGES) * STAGE_FLOATS;
        const float* Bs = As + A_STAGE;
#pragma unroll
        for (int ks = 0; ks < 4; ks++) {
            const int kk = ks << 3;
            unsigned a[2][4];
#pragma unroll
            for (int mi = 0; mi < 2; mi++) {
                int row = (wm << 5) + (mi << 4);
                a[mi][0] = f2tf32(As[(row + g) * AS_STRIDE + kk + tg]);
                a[mi][1] = f2tf32(As[(row + g + 8) * AS_STRIDE + kk + tg]);
                a[mi][2] = f2tf32(As[(row + g) * AS_STRIDE + kk + tg + 4]);
                a[mi][3] = f2tf32(As[(row + g + 8) * AS_STRIDE + kk + tg + 4]);
            }
#pragma unroll
            for (int f = 0; f < 10; f++) {
                int c = wn * 80 + (f << 3) + g;
                unsigned bb0 = __float_as_uint(Bs[(kk + tg) * BS_STRIDE + c]);
                unsigned bb1 = __float_as_uint(Bs[(kk + tg + 4) * BS_STRIDE + c]);
                mma_tf32(acc[0][f], a[0], bb0, bb1);
                mma_tf32(acc[1][f], a[1], bb0, bb1);
            }
        }
    }
    __syncthreads();
    // stage z to smem (fp32)
#pragma unroll
    for (int mi = 0; mi < 2; mi++)
#pragma unroll
        for (int f = 0; f < 10; f++) {
            int rb = (wm << 5) + (mi << 4) + g;
            int cb = wn * 80 + (f << 3) + (tg << 1);
            Zs[rb * ZS_STRIDE + cb] = acc[mi][f][0];
            Zs[rb * ZS_STRIDE + cb + 1] = acc[mi][f][1];
            Zs[(rb + 8) * ZS_STRIDE + cb] = acc[mi][f][2];
            Zs[(rb + 8) * ZS_STRIDE + cb + 1] = acc[mi][f][3];
        }
    __syncthreads();

    // ---- elementwise gate fusion ----
    const float* brow = bias + (l * NB + j) * FIVEH;
    const float* ctp; int cts;
    if (t == 0)      { ctp = g_rowc + (j * BB + b0) * HH; cts = HH; }
    else if (l == 0) { ctp = g_c0 + (((t - 1) * NB + j) * BB + b0) * HH; cts = HH; }
    else             { ctp = outc + ((b0 * TOUT + (t - 1)) * NB + j) * HH; cts = TOUT * NB * HH; }
    const float* csp; int css;
    if (j == 0)      { csp = g_colc + b0 * HH; css = HH; }
    else if (l == 0) { csp = g_c0 + ((t * NB + (j - 1)) * BB + b0) * HH; css = HH; }
    else             { csp = outc + ((b0 * TOUT + t) * NB + (j - 1)) * HH; css = TOUT * NB * HH; }

    float *oh, *oc; int os;
    if (l == 0) {
        oh = g_h0 + ((t * NB + j) * BB + b0) * HH;
        oc = g_c0 + ((t * NB + j) * BB + b0) * HH;
        os = HH;
    } else {
        oh = outh + ((b0 * TOUT + t) * NB + j) * HH;
        oc = outc + ((b0 * TOUT + t) * NB + j) * HH;
        os = TOUT * NB * HH;
    }

    for (int e = tid; e < 128 * 32; e += 256) {
        int m = e >> 5, hh = e & 31;
        int ha = h0 + hh;
        // gate order: i, f_s, f_t, o, g
        float zi = Zs[m * ZS_STRIDE + hh] + brow[ha];
        float zfs = Zs[m * ZS_STRIDE + 32 + hh] + brow[128 + ha];
        float zft = Zs[m * ZS_STRIDE + 64 + hh] + brow[256 + ha];
        float zo = Zs[m * ZS_STRIDE + 96 + hh] + brow[384 + ha];
        float zg = Zs[m * ZS_STRIDE + 128 + hh] + brow[512 + ha];
        float ctv = ctp[m * cts + ha];
        float csv = csp[m * css + ha];
        float cv = sigm(zi) * tanh_fast(zg) + sigm(zft) * ctv + sigm(zfs) * csv;
        float hv = sigm(zo) * tanh_fast(cv);
        oh[m * os + ha] = hv;
        oc[m * os + ha] = cv;
    }
}

// Combined-layer diagonal wavefront: layer0 cell (t,j) at d=t+j, layer1 at d=t+j+1.
// All dependencies land in diagonal d-1 -> one grid barrier per diagonal (49 total).
__global__ void __launch_bounds__(256)
st_main(const float* __restrict__ p, const float* __restrict__ bias,
        float* __restrict__ outh, float* __restrict__ outc) {
    extern __shared__ char smem_raw[];
    unsigned long long gen = 0;
    for (int d = 0; d < TOUT + NB; d++) {  // d = 0..48
        int lo0 = (d - (NB - 1) > 0) ? d - (NB - 1) : 0;
        int hi0 = (d < TOUT - 1) ? d : TOUT - 1;
        int n0 = hi0 - lo0 + 1;
        if (n0 < 0) n0 = 0;
        int e = d - 1;
        int lo1 = 0, n1 = 0;
        if (e >= 0) {
            lo1 = (e - (NB - 1) > 0) ? e - (NB - 1) : 0;
            int hi1 = (e < TOUT - 1) ? e : TOUT - 1;
            n1 = hi1 - lo1 + 1;
            if (n1 < 0) n1 = 0;
        }
        int items = (n0 + n1) << 3;
        for (int it = blockIdx.x; it < items; it += gridDim.x) {
            int cell = it >> 3;
            int l, t, jj;
            if (cell < n0) { l = 0; t = lo0 + cell; jj = d - t; }
            else           { l = 1; t = lo1 + (cell - n0); jj = e - t; }
            process_cell_tile(t, jj, l, (it >> 2) & 1, it & 3, p, bias, outh, outc, smem_raw);
        }
        // grid barrier (monotonic counter; reset each launch by prep_weights)
        gen++;
        __syncthreads();
        if (threadIdx.x == 0) {
            __threadfence();
            atomicAdd(&g_bar, 1ULL);
            unsigned long long target = gen * (unsigned long long)gridDim.x;
            while (*(volatile unsigned long long*)&g_bar < target) __nanosleep(32);
            __threadfence();
        }
        __syncthreads();
    }
}

// ---------------- launch ----------------
extern "C" void kernel_launch(void* const* d_in, const int* in_sizes, int n_in,
                              void* d_out, int out_size) {
    const float* hs = (const float*)d_in[0];
    const float* cs = (const float*)d_in[1];
    const float* gts = (const float*)d_in[2];
    const float* p = (const float*)d_in[3];
    const float* U = (const float*)d_in[4];
    const float* Wt = (const float*)d_in[5];
    const float* Ws = (const float*)d_in[6];
    const float* b = (const float*)d_in[7];

    float* outh = (float*)d_out;
    float* outc = outh + (size_t)BB * TOUT * NB * HH;

    prep_weights<<<2048, 256>>>(U, Wt, Ws);
    prep_rows<<<(NB * BB * HH + 255) / 256, 256>>>(hs, cs, gts);
    prep_cols<<<(BB * HH + 255) / 256, 256>>>();

    int dev = 0;
    cudaGetDevice(&dev);
    int nsm = 148;
    cudaDeviceGetAttribute(&nsm, cudaDevAttrMultiProcessorCount, dev);
    cudaFuncSetAttribute(st_main, cudaFuncAttributeMaxDynamicSharedMemorySize, SMEM_BYTES);
    st_main<<<nsm, 256, SMEM_BYTES>>>(p, b, outh, outc);
}

// round 4
// speedup vs baseline: 1.8493x; 1.4163x over previous
#include <cuda_runtime.h>
#include <math.h>

#define BB 256
#define TIN 49
#define TOUT 25
#define NB 24
#define HH 128
#define FIVEH 640
#define KTOT 384

// ---------------- device scratch (no allocations allowed) ----------------
__device__ float g_Wcat[2 * NB * KTOT * FIVEH];   // [l][j][k][n], tf32-rounded
__device__ float g_P0[BB * TOUT * NB * FIVEH];    // p @ U[0], [b][t][j][640]  (393MB)
__device__ float g_h0[TOUT * NB * BB * HH];       // layer-0 h, [t][j][b][h]
__device__ float g_c0[TOUT * NB * BB * HH];       // layer-0 c
__device__ float g_rowh[2 * NB * BB * HH];        // [l][j][b][h] initial temporal h
__device__ float g_rowc[NB * BB * HH];            // [j][b][h]   initial temporal c
__device__ float g_colh[BB * HH];                 // [b][h]      initial spatial h
__device__ float g_colc[BB * HH];                 // [b][h]      initial spatial c
__device__ unsigned long long g_bar;              // grid barrier counter

// ---------------- helpers ----------------
__device__ __forceinline__ float sigm(float x) { return 1.0f / (1.0f + __expf(-x)); }
__device__ __forceinline__ float tanh_fast(float x) { return 2.0f / (1.0f + __expf(-2.0f * x)) - 1.0f; }

__device__ __forceinline__ unsigned f2tf32(float v) {
    unsigned u;
    asm("cvt.rna.tf32.f32 %0, %1;" : "=r"(u) : "f"(v));
    return u;
}

__device__ __forceinline__ void mma_tf32(float* c, const unsigned* a, unsigned b0, unsigned b1) {
    asm volatile(
        "mma.sync.aligned.m16n8k8.row.col.f32.tf32.tf32.f32 "
        "{%0,%1,%2,%3}, {%4,%5,%6,%7}, {%8,%9}, {%0,%1,%2,%3};\n"
        : "+f"(c[0]), "+f"(c[1]), "+f"(c[2]), "+f"(c[3])
        : "r"(a[0]), "r"(a[1]), "r"(a[2]), "r"(a[3]), "r"(b0), "r"(b1));
}

__device__ __forceinline__ void cp16(float* dst_smem, const float* src_gmem) {
    unsigned d = (unsigned)__cvta_generic_to_shared(dst_smem);
    asm volatile("cp.async.cg.shared.global [%0], [%1], 16;\n" ::"r"(d), "l"(src_gmem));
}
__device__ __forceinline__ void cp_commit() { asm volatile("cp.async.commit_group;\n"); }
template <int N>
__device__ __forceinline__ void cp_wait() { asm volatile("cp.async.wait_group %0;\n" ::"n"(N)); }

// ---------------- prep kernels ----------------
__global__ void prep_weights(const float* __restrict__ U, const float* __restrict__ Wt,
                             const float* __restrict__ Ws) {
    const int total = 2 * NB * KTOT * FIVEH;
    for (int i = blockIdx.x * blockDim.x + threadIdx.x; i < total; i += gridDim.x * blockDim.x) {
        int n = i % FIVEH;
        int r = i / FIVEH;
        int k = r % KTOT;
        int lj = r / KTOT;
        const float* src;
        int kk = k;
        if (k < HH) { src = U; }
        else if (k < 2 * HH) { src = Wt; kk = k - HH; }
        else { src = Ws; kk = k - 2 * HH; }
        float v = src[(lj * HH + kk) * FIVEH + n];
        g_Wcat[i] = __uint_as_float(f2tf32(v));
    }
    if (blockIdx.x == 0 && threadIdx.x == 0) g_bar = 0ULL;
}

__global__ void prep_rows(const float* __restrict__ hs, const float* __restrict__ cs,
                          const float* __restrict__ gts) {
    int i = blockIdx.x * blockDim.x + threadIdx.x;
    const int total = NB * BB * HH;
    if (i >= total) return;
    int h = i % HH;
    int b = (i / HH) % BB;
    int j = i / (HH * BB);
    const float* ph = hs + (b * TIN * NB + j) * HH + h;
    const float* pc = cs + (b * TIN * NB + j) * HH + h;
    float sh = 0.f, sc = 0.f;
    for (int t = 0; t < TIN; t++) { sh += ph[t * NB * HH]; sc += pc[t * NB * HH]; }
    float gv = gts[(b * NB + j) * HH + h];
    g_rowh[(0 * NB + j) * BB * HH + b * HH + h] = sh / 49.0f;
    g_rowh[(1 * NB + j) * BB * HH + b * HH + h] = (sh + gv) / 50.0f;
    g_rowc[j * BB * HH + b * HH + h] = sc / 49.0f;
}

__global__ void prep_cols() {
    int i = blockIdx.x * blockDim.x + threadIdx.x;
    if (i >= BB * HH) return;
    float sh = 0.f, sc = 0.f;
    for (int j = 0; j < NB; j++) {
        sh += g_rowh[j * BB * HH + i];
        sc += g_rowc[j * BB * HH + i];
    }
    g_colh[i] = sh / (float)NB;
    g_colc[i] = sc / (float)NB;
}

// =====================================================================
// PRE-PASS: g_P0[b][t][j][n] = p[b,t,j,:] @ U0[j][:,n]   (tf32 mma)
// For fixed j: GEMM [6400 x 128] @ [128 x 640]. Tile M=128, N=160, K=128.
// 256 threads, 8 warps as 4(M) x 2(N), 3-stage cp.async.
// =====================================================================
#define PP_AS 36
#define PP_BS 168
#define PP_A_FLOATS (128 * PP_AS)
#define PP_B_FLOATS (32 * PP_BS)
#define PP_STAGE (PP_A_FLOATS + PP_B_FLOATS)         // 9984 floats
#define PP_SMEM (3 * PP_STAGE * 4)                   // 119808 B

__device__ __forceinline__ void pp_issue(const float* __restrict__ asrc, int astr, int hoff,
                                         const float* __restrict__ wsrc, int n0, float* stage) {
    float* As = stage;
    float* Bs = stage + PP_A_FLOATS;
    const int tid = threadIdx.x;
#pragma unroll
    for (int i = 0; i < 4; i++) {
        int idx = tid + (i << 8);
        int r = idx >> 3;
        int c4 = (idx & 7) << 2;
        cp16(As + r * PP_AS + c4, asrc + r * astr + hoff + c4);
    }
#pragma unroll
    for (int i = 0; i < 5; i++) {
        int idx = tid + (i << 8);
        int k = idx / 40;
        int cc = (idx % 40) << 2;
        cp16(Bs + k * PP_BS + cc, wsrc + k * FIVEH + n0 + cc);
    }
}

__global__ void __launch_bounds__(256)
prepass(const float* __restrict__ p) {
    extern __shared__ float smem[];
    int bx = blockIdx.x;
    int j = bx / 200;
    int rem = bx % 200;
    int r0 = (rem >> 2) << 7;   // M offset (row = b*TOUT + t), 0..6272
    int n0 = (rem & 3) * 160;   // N offset into 640

    const int tid = threadIdx.x;
    const int warp = tid >> 5, lane = tid & 31;
    const int wm = warp >> 1, wn = warp & 1;
    const int g = lane >> 2, tg = lane & 3;

    const float* asrc = p + (r0 * NB + j) * HH;
    const int astr = NB * HH;
    const float* wsrc = g_Wcat + j * (KTOT * FIVEH);   // l=0 block, k rows 0..127 = U

    float acc[2][10][4];
#pragma unroll
    for (int i = 0; i < 2; i++)
#pragma unroll
        for (int f = 0; f < 10; f++)
#pragma unroll
            for (int ci = 0; ci < 4; ci++) acc[i][f][ci] = 0.0f;

    pp_issue(asrc, astr, 0, wsrc, n0, smem);
    cp_commit();
    pp_issue(asrc, astr, 32, wsrc + 32 * FIVEH, n0, smem + PP_STAGE);
    cp_commit();

    for (int kc = 0; kc < 4; kc++) {
        cp_wait<1>();
        __syncthreads();
        int nxt = kc + 2;
        if (nxt < 4) {
            pp_issue(asrc, astr, nxt << 5, wsrc + (nxt << 5) * FIVEH, n0,
                     smem + (nxt % 3) * PP_STAGE);
        }
        cp_commit();
        const float* As = smem + (kc % 3) * PP_STAGE;
        const float* Bs = As + PP_A_FLOATS;
#pragma unroll
        for (int ks = 0; ks < 4; ks++) {
            const int kk = ks << 3;
            unsigned a[2][4];
#pragma unroll
            for (int mi = 0; mi < 2; mi++) {
                int row = (wm << 5) + (mi << 4);
                a[mi][0] = f2tf32(As[(row + g) * PP_AS + kk + tg]);
                a[mi][1] = f2tf32(As[(row + g + 8) * PP_AS + kk + tg]);
                a[mi][2] = f2tf32(As[(row + g) * PP_AS + kk + tg + 4]);
                a[mi][3] = f2tf32(As[(row + g + 8) * PP_AS + kk + tg + 4]);
            }
#pragma unroll
            for (int f = 0; f < 10; f++) {
                int c = wn * 80 + (f << 3) + g;
                unsigned b0r = __float_as_uint(Bs[(kk + tg) * PP_BS + c]);
                unsigned b1r = __float_as_uint(Bs[(kk + tg + 4) * PP_BS + c]);
                mma_tf32(acc[0][f], a[0], b0r, b1r);
                mma_tf32(acc[1][f], a[1], b0r, b1r);
            }
        }
        __syncthreads();
    }

    // direct store to g_P0 (rows r = b*TOUT+t -> P0[(r*NB+j)*640 + n])
#pragma unroll
    for (int mi = 0; mi < 2; mi++)
#pragma unroll
        for (int f = 0; f < 10; f++) {
            int r1 = r0 + (wm << 5) + (mi << 4) + g;
            int nl = n0 + wn * 80 + (f << 3) + (tg << 1);
            float2 v0 = make_float2(acc[mi][f][0], acc[mi][f][1]);
            float2 v1 = make_float2(acc[mi][f][2], acc[mi][f][3]);
            *(float2*)(g_P0 + (r1 * NB + j) * FIVEH + nl) = v0;
            *(float2*)(g_P0 + ((r1 + 8) * NB + j) * FIVEH + nl) = v1;
        }
}

// =====================================================================
// MAIN wavefront kernel.
// CTA: 128 threads (4 warps as 2Mx2N), tile M=64 x N=160, K-chunk 32.
// layer0: 8 chunks (h_t@Wt + h_s@Ws), P0 added in epilogue. layer1: 12 chunks.
// 2 CTAs/SM; grid barrier per diagonal.
// =====================================================================
#define WF_AS 36
#define WF_BS 168
#define WF_ZS 161
#define WF_A_FLOATS (64 * WF_AS)                    // 2304
#define WF_B_FLOATS (32 * WF_BS)                    // 5376
#define WF_STAGE (WF_A_FLOATS + WF_B_FLOATS)        // 7680 floats
#define WF_SMEM (3 * WF_STAGE * 4)                  // 92160 B

__device__ __forceinline__ void wf_issue(const float* __restrict__ asrc, int astr, int hoff,
                                         const float* __restrict__ wsrc, int h0, float* stage) {
    float* As = stage;
    float* Bs = stage + WF_A_FLOATS;
    const int tid = threadIdx.x;
#pragma unroll
    for (int i = 0; i < 4; i++) {   // A: 64 rows x 8 x 16B = 512 cp16
        int idx = tid + (i << 7);
        int r = idx >> 3;
        int c4 = (idx & 7) << 2;
        cp16(As + r * WF_AS + c4, asrc + r * astr + hoff + c4);
    }
#pragma unroll
    for (int i = 0; i < 10; i++) {  // B: 32 rows x 40 x 16B = 1280 cp16
        int idx = tid + (i << 7);
        int k = idx / 40;
        int cc = (idx % 40) << 2;
        int n = ((cc >> 5) << 7) + h0 + (cc & 31);
        cp16(Bs + k * WF_BS + cc, wsrc + k * FIVEH + n);
    }
}

__device__ void process_cell_tile(int t, int j, int l, int mtile, int htile,
                                  const float* __restrict__ bias,
                                  float* __restrict__ outh, float* __restrict__ outc,
                                  float* smem) {
    float* Zs = smem;  // [64][161], overlaps stages (sync-guarded)
    const int tid = threadIdx.x;
    const int warp = tid >> 5, lane = tid & 31;
    const int wm = warp >> 1, wn = warp & 1;
    const int g = lane >> 2, tg = lane & 3;
    const int b0 = mtile << 6;
    const int h0 = htile << 5;

    // A sources + weight-row offset
    const float* srcs[3];
    int strides[3];
    int nsrc_chunks, wkoff;
    if (l == 0) {
        wkoff = HH;  nsrc_chunks = 8;
        // src0 = h_t, src1 = h_s
        if (t == 0) { srcs[0] = g_rowh + ((0 * NB + j) * BB + b0) * HH; strides[0] = HH; }
        else        { srcs[0] = g_h0 + (((t - 1) * NB + j) * BB + b0) * HH; strides[0] = HH; }
        if (j == 0) { srcs[1] = g_colh + b0 * HH; strides[1] = HH; }
        else        { srcs[1] = g_h0 + ((t * NB + (j - 1)) * BB + b0) * HH; strides[1] = HH; }
        srcs[2] = srcs[1]; strides[2] = strides[1];  // unused
    } else {
        wkoff = 0;   nsrc_chunks = 12;
        srcs[0] = g_h0 + ((t * NB + j) * BB + b0) * HH; strides[0] = HH;
        if (t == 0) { srcs[1] = g_rowh + ((1 * NB + j) * BB + b0) * HH; strides[1] = HH; }
        else        { srcs[1] = outh + ((b0 * TOUT + (t - 1)) * NB + j) * HH; strides[1] = TOUT * NB * HH; }
        if (j == 0) { srcs[2] = g_colh + b0 * HH; strides[2] = HH; }
        else        { srcs[2] = outh + ((b0 * TOUT + t) * NB + (j - 1)) * HH; strides[2] = TOUT * NB * HH; }
    }
    const float* wlj = g_Wcat + (l * NB + j) * (KTOT * FIVEH) + wkoff * FIVEH;

    float acc[2][10][4];
#pragma unroll
    for (int i = 0; i < 2; i++)
#pragma unroll
        for (int f = 0; f < 10; f++)
#pragma unroll
            for (int ci = 0; ci < 4; ci++) acc[i][f][ci] = 0.0f;

    __syncthreads();  // previous tile's Zs fully consumed

    wf_issue(srcs[0], strides[0], 0, wlj, h0, smem);
    cp_commit();
    wf_issue(srcs[0], strides[0], 32, wlj + 32 * FIVEH, h0, smem + WF_STAGE);
    cp_commit();

    const int nc = nsrc_chunks;
    for (int kc = 0; kc < nc; kc++) {
        cp_wait<1>();
        __syncthreads();
        int nxt = kc + 2;
        if (nxt < nc) {
            wf_issue(srcs[nxt >> 2], strides[nxt >> 2], (nxt & 3) << 5,
                     wlj + (nxt << 5) * FIVEH, h0, smem + (nxt % 3) * WF_STAGE);
        }
        cp_commit();
        const float* As = smem + (kc % 3) * WF_STAGE;
        const float* Bs = As + WF_A_FLOATS;
#pragma unroll
        for (int ks = 0; ks < 4; ks++) {
            const int kk = ks << 3;
            unsigned a[2][4];
#pragma unroll
            for (int mi = 0; mi < 2; mi++) {
                int row = (wm << 5) + (mi << 4);
                a[mi][0] = f2tf32(As[(row + g) * WF_AS + kk + tg]);
                a[mi][1] = f2tf32(As[(row + g + 8) * WF_AS + kk + tg]);
                a[mi][2] = f2tf32(As[(row + g) * WF_AS + kk + tg + 4]);
                a[mi][3] = f2tf32(As[(row + g + 8) * WF_AS + kk + tg + 4]);
            }
#pragma unroll
            for (int f = 0; f < 10; f++) {
                int c = wn * 80 + (f << 3) + g;
                unsigned b0r = __float_as_uint(Bs[(kk + tg) * WF_BS + c]);
                unsigned b1r = __float_as_uint(Bs[(kk + tg + 4) * WF_BS + c]);
                mma_tf32(acc[0][f], a[0], b0r, b1r);
                mma_tf32(acc[1][f], a[1], b0r, b1r);
            }
        }
    }
    __syncthreads();
#pragma unroll
    for (int mi = 0; mi < 2; mi++)
#pragma unroll
        for (int f = 0; f < 10; f++) {
            int rb = (wm << 5) + (mi << 4) + g;
            int cb = wn * 80 + (f << 3) + (tg << 1);
            Zs[rb * WF_ZS + cb] = acc[mi][f][0];
            Zs[rb * WF_ZS + cb + 1] = acc[mi][f][1];
            Zs[(rb + 8) * WF_ZS + cb] = acc[mi][f][2];
            Zs[(rb + 8) * WF_ZS + cb + 1] = acc[mi][f][3];
        }
    __syncthreads();

    // ---- elementwise gate fusion ----
    const float* brow = bias + (l * NB + j) * FIVEH;
    const float* ctp; int cts;
    if (t == 0)      { ctp = g_rowc + (j * BB + b0) * HH; cts = HH; }
    else if (l == 0) { ctp = g_c0 + (((t - 1) * NB + j) * BB + b0) * HH; cts = HH; }
    else             { ctp = outc + ((b0 * TOUT + (t - 1)) * NB + j) * HH; cts = TOUT * NB * HH; }
    const float* csp; int css;
    if (j == 0)      { csp = g_colc + b0 * HH; css = HH; }
    else if (l == 0) { csp = g_c0 + ((t * NB + (j - 1)) * BB + b0) * HH; css = HH; }
    else             { csp = outc + ((b0 * TOUT + t) * NB + (j - 1)) * HH; css = TOUT * NB * HH; }

    float *oh, *oc; int os;
    if (l == 0) {
        oh = g_h0 + ((t * NB + j) * BB + b0) * HH;
        oc = g_c0 + ((t * NB + j) * BB + b0) * HH;
        os = HH;
    } else {
        oh = outh + ((b0 * TOUT + t) * NB + j) * HH;
        oc = outc + ((b0 * TOUT + t) * NB + j) * HH;
        os = TOUT * NB * HH;
    }

    for (int e = tid; e < 64 * 32; e += 128) {
        int m = e >> 5, hh = e & 31;
        int ha = h0 + hh;
        float zi  = Zs[m * WF_ZS + hh];
        float zfs = Zs[m * WF_ZS + 32 + hh];
        float zft = Zs[m * WF_ZS + 64 + hh];
        float zo  = Zs[m * WF_ZS + 96 + hh];
        float zg  = Zs[m * WF_ZS + 128 + hh];
        if (l == 0) {
            const float* p0 = g_P0 + (((b0 + m) * TOUT + t) * NB + j) * FIVEH;
            zi += p0[ha]; zfs += p0[128 + ha]; zft += p0[256 + ha];
            zo += p0[384 + ha]; zg += p0[512 + ha];
        }
        zi += brow[ha]; zfs += brow[128 + ha]; zft += brow[256 + ha];
        zo += brow[384 + ha]; zg += brow[512 + ha];
        float ctv = ctp[m * cts + ha];
        float csv = csp[m * css + ha];
        float cv = sigm(zi) * tanh_fast(zg) + sigm(zft) * ctv + sigm(zfs) * csv;
        float hv = sigm(zo) * tanh_fast(cv);
        oh[m * os + ha] = hv;
        oc[m * os + ha] = cv;
    }
}

__global__ void __launch_bounds__(128, 2)
st_main(const float* __restrict__ bias, float* __restrict__ outh, float* __restrict__ outc) {
    extern __shared__ float smem[];
    unsigned long long gen = 0;
    for (int d = 0; d < TOUT + NB; d++) {  // 49 diagonals
        int lo0 = (d - (NB - 1) > 0) ? d - (NB - 1) : 0;
        int hi0 = (d < TOUT - 1) ? d : TOUT - 1;
        int n0 = hi0 - lo0 + 1;
        if (n0 < 0) n0 = 0;
        int e = d - 1;
        int lo1 = 0, n1 = 0;
        if (e >= 0) {
            lo1 = (e - (NB - 1) > 0) ? e - (NB - 1) : 0;
            int hi1 = (e < TOUT - 1) ? e : TOUT - 1;
            n1 = hi1 - lo1 + 1;
            if (n1 < 0) n1 = 0;
        }
        int items = (n0 + n1) << 4;  // 16 tiles/cell (4 mtiles x 4 htiles)
        for (int it = blockIdx.x; it < items; it += gridDim.x) {
            int cell = it >> 4;
            int l, t, jj;
            if (cell < n0) { l = 0; t = lo0 + cell; jj = d - t; }
            else           { l = 1; t = lo1 + (cell - n0); jj = e - t; }
            process_cell_tile(t, jj, l, (it >> 2) & 3, it & 3, bias, outh, outc, smem);
        }
        gen++;
        __syncthreads();
        if (threadIdx.x == 0) {
            __threadfence();
            atomicAdd(&g_bar, 1ULL);
            unsigned long long target = gen * (unsigned long long)gridDim.x;
            while (*(volatile unsigned long long*)&g_bar < target) __nanosleep(32);
            __threadfence();
        }
        __syncthreads();
    }
}

// ---------------- launch ----------------
extern "C" void kernel_launch(void* const* d_in, const int* in_sizes, int n_in,
                              void* d_out, int out_size) {
    const float* hs = (const float*)d_in[0];
    const float* cs = (const float*)d_in[1];
    const float* gts = (const float*)d_in[2];
    const float* p = (const float*)d_in[3];
    const float* U = (const float*)d_in[4];
    const float* Wt = (const float*)d_in[5];
    const float* Ws = (const float*)d_in[6];
    const float* b = (const float*)d_in[7];

    float* outh = (float*)d_out;
    float* outc = outh + (size_t)BB * TOUT * NB * HH;

    prep_weights<<<2048, 256>>>(U, Wt, Ws);
    prep_rows<<<(NB * BB * HH + 255) / 256, 256>>>(hs, cs, gts);
    prep_cols<<<(BB * HH + 255) / 256, 256>>>();

    cudaFuncSetAttribute(prepass, cudaFuncAttributeMaxDynamicSharedMemorySize, PP_SMEM);
    prepass<<<24 * 200, 256, PP_SMEM>>>(p);

    int dev = 0;
    cudaGetDevice(&dev);
    int nsm = 148;
    cudaDeviceGetAttribute(&nsm, cudaDevAttrMultiProcessorCount, dev);
    cudaFuncSetAttribute(st_main, cudaFuncAttributeMaxDynamicSharedMemorySize, WF_SMEM);
    int occ = 0;
    cudaOccupancyMaxActiveBlocksPerMultiprocessor(&occ, st_main, 128, WF_SMEM);
    if (occ < 1) occ = 1;
    if (occ > 2) occ = 2;
    st_main<<<nsm * occ, 128, WF_SMEM>>>(b, outh, outc);
}

// round 7
// speedup vs baseline: 2.0590x; 1.1134x over previous
#include <cuda_runtime.h>
#include <math.h>

#define BB 256
#define TIN 49
#define TOUT 25
#define NB 24
#define HH 128
#define FIVEH 640
#define KTOT 384

#define WCHUNK_FLOATS 5120  // one (lj,kc,ht) B chunk: 5 gates x 32 cols x 4 tg x 8 s

// ---------------- device scratch ----------------
// fragment-major weights: [lj(48)][kc(12)][ht(4)][gate(5)][hh(32)][tg(4)][s(8)]
__device__ float g_Wfrag[48 * 12 * 4 * WCHUNK_FLOATS];   // 11,796,480 floats = 45 MB
__device__ float g_P0[BB * TOUT * NB * FIVEH];    // p @ U[0]
__device__ float g_h0[TOUT * NB * BB * HH];       // layer-0 h (tf32-rounded)
__device__ float g_c0[TOUT * NB * BB * HH];       // layer-0 c (full)
__device__ float g_h1r[TOUT * NB * BB * HH];      // layer-1 h rounded shadow
__device__ float g_rowh[2 * NB * BB * HH];        // full (for prep_cols)
__device__ float g_rowh_r[2 * NB * BB * HH];      // rounded (A operand)
__device__ float g_rowc[NB * BB * HH];
__device__ float g_colh_r[BB * HH];               // rounded (A operand)
__device__ float g_colc[BB * HH];
__device__ unsigned long long g_bar;

// ---------------- helpers ----------------
__device__ __forceinline__ float sigm(float x) { return 1.0f / (1.0f + __expf(-x)); }
__device__ __forceinline__ float tanh_fast(float x) { return 2.0f / (1.0f + __expf(-2.0f * x)) - 1.0f; }

__device__ __forceinline__ unsigned f2tf32(float v) {
    unsigned u;
    asm("cvt.rna.tf32.f32 %0, %1;" : "=r"(u) : "f"(v));
    return u;
}
__device__ __forceinline__ float f2tf32f(float v) { return __uint_as_float(f2tf32(v)); }

__device__ __forceinline__ void mma_tf32(float* c, const unsigned* a, unsigned b0, unsigned b1) {
    asm volatile(
        "mma.sync.aligned.m16n8k8.row.col.f32.tf32.tf32.f32 "
        "{%0,%1,%2,%3}, {%4,%5,%6,%7}, {%8,%9}, {%0,%1,%2,%3};\n"
        : "+f"(c[0]), "+f"(c[1]), "+f"(c[2]), "+f"(c[3])
        : "r"(a[0]), "r"(a[1]), "r"(a[2]), "r"(a[3]), "r"(b0), "r"(b1));
}

__device__ __forceinline__ void cp16(float* dst_smem, const float* src_gmem) {
    unsigned d = (unsigned)__cvta_generic_to_shared(dst_smem);
    asm volatile("cp.async.cg.shared.global [%0], [%1], 16;\n" ::"r"(d), "l"(src_gmem));
}
__device__ __forceinline__ void cp_commit() { asm volatile("cp.async.commit_group;\n"); }
template <int N>
__device__ __forceinline__ void cp_wait() { asm volatile("cp.async.wait_group %0;\n" ::"n"(N)); }

// ---------------- prep: fragment-major weight pack ----------------
// grid: lj(48) x kc(12) x ht(4) x gate(5) = 11520 blocks, 128 threads
__global__ void prep_wfrag(const float* __restrict__ U, const float* __restrict__ Wt,
                           const float* __restrict__ Ws) {
    __shared__ float tile[32][33];
    int bx = blockIdx.x;
    int gate = bx % 5;
    int ht = (bx / 5) & 3;
    int kc = (bx / 20) % 12;
    int lj = bx / 240;
    int tx = threadIdx.x & 31, ty = threadIdx.x >> 5;

    const float* src;
    int kbase;
    if (kc < 4) { src = U; kbase = kc * 32; }
    else if (kc < 8) { src = Wt; kbase = (kc - 4) * 32; }
    else { src = Ws; kbase = (kc - 8) * 32; }
    int n0 = gate * 128 + ht * 32;

    for (int kk = ty; kk < 32; kk += 4) {
        float v = src[((size_t)lj * HH + kbase + kk) * FIVEH + n0 + tx];
        tile[kk][tx] = f2tf32f(v);
    }
    __syncthreads();
    float* out = g_Wfrag + ((size_t)(lj * 12 + kc) * 4 + ht) * WCHUNK_FLOATS + gate * 1024;
    int q = tx;
    int kk = (q >> 3) + ((q & 7) << 2);  // tg = q>>3, s = q&7, k-row = tg + 4s
    for (int hh = ty; hh < 32; hh += 4) {
        out[hh * 32 + q] = tile[kk][hh];
    }
    if (bx == 0 && threadIdx.x == 0) g_bar = 0ULL;
}

// ---------------- prep: row/col means ----------------
__global__ void prep_rows(const float* __restrict__ hs, const float* __restrict__ cs,
                          const float* __restrict__ gts) {
    int i = blockIdx.x * blockDim.x + threadIdx.x;
    const int total = NB * BB * HH;
    if (i >= total) return;
    int h = i % HH;
    int b = (i / HH) % BB;
    int j = i / (HH * BB);
    const float* ph = hs + (b * TIN * NB + j) * HH + h;
    const float* pc = cs + (b * TIN * NB + j) * HH + h;
    float sh = 0.f, sc = 0.f;
    for (int t = 0; t < TIN; t++) { sh += ph[t * NB * HH]; sc += pc[t * NB * HH]; }
    float gv = gts[(b * NB + j) * HH + h];
    float r0 = sh / 49.0f, r1 = (sh + gv) / 50.0f;
    int o0 = (0 * NB + j) * BB * HH + b * HH + h;
    int o1 = (1 * NB + j) * BB * HH + b * HH + h;
    g_rowh[o0] = r0; g_rowh[o1] = r1;
    g_rowh_r[o0] = f2tf32f(r0);
    g_rowh_r[o1] = f2tf32f(r1);
    g_rowc[j * BB * HH + b * HH + h] = sc / 49.0f;
}

__global__ void prep_cols() {
    int i = blockIdx.x * blockDim.x + threadIdx.x;
    if (i >= BB * HH) return;
    float sh = 0.f, sc = 0.f;
    for (int j = 0; j < NB; j++) {
        sh += g_rowh[j * BB * HH + i];
        sc += g_rowc[j * BB * HH + i];
    }
    g_colh_r[i] = f2tf32f(sh / (float)NB);
    g_colc[i] = sc / (float)NB;
}

// =====================================================================
// PRE-PASS: g_P0 = p @ U0. Tile M=128, N=160 (gate-strided), K=128.
// 256 threads = 8 warps (4M x 2N). A via 3-stage cp.async (cvt at consume);
// B via direct LDG.128 from g_Wfrag.
// =====================================================================
#define PP_AS 36
#define PP_A_FLOATS (128 * PP_AS)
#define PP_SMEM (3 * PP_A_FLOATS * 4)   // 55296

__global__ void __launch_bounds__(256)
prepass(const float* __restrict__ p) {
    extern __shared__ float smem[];
    int bx = blockIdx.x;
    int j = bx / 200;
    int rem = bx % 200;
    int r0 = (rem >> 2) << 7;   // row = b*TOUT + t
    int ht = rem & 3;

    const int tid = threadIdx.x;
    const int warp = tid >> 5, lane = tid & 31;
    const int wm = warp >> 1, wn = warp & 1;
    const int g = lane >> 2, tg = lane & 3;

    const float* asrc = p + (r0 * NB + j) * HH;
    const int astr = NB * HH;
    const float4* wbase = (const float4*)(g_Wfrag + ((size_t)(j * 12 + 0) * 4 + ht) * WCHUNK_FLOATS);
    const int bo4 = ((wn * 16 + g) << 3) + (tg << 1);

    float acc[2][10][4];
#pragma unroll
    for (int i = 0; i < 2; i++)
#pragma unroll
        for (int f = 0; f < 10; f++)
#pragma unroll
            for (int ci = 0; ci < 4; ci++) acc[i][f][ci] = 0.0f;

#define PP_ISSUE(hoff, stg)                                                   \
    {                                                                         \
        float* As = smem + (stg) * PP_A_FLOATS;                               \
        _Pragma("unroll") for (int i = 0; i < 4; i++) {                       \
            int idx = tid + (i << 8);                                         \
            int r = idx >> 3;                                                 \
            int c4 = (idx & 7) << 2;                                          \
            cp16(As + r * PP_AS + c4, asrc + r * astr + (hoff) + c4);         \
        }                                                                     \
    }

    PP_ISSUE(0, 0); cp_commit();
    PP_ISSUE(32, 1); cp_commit();

    for (int kc = 0; kc < 4; kc++) {
        cp_wait<1>();
        __syncthreads();
        if (kc < 2) { PP_ISSUE((kc + 2) << 5, (kc + 2) % 3); }
        cp_commit();

        const float* Asf = smem + (kc % 3) * PP_A_FLOATS;
        unsigned av[4][2][4];
#pragma unroll
        for (int ks = 0; ks < 4; ks++) {
            int col = (ks << 3) + tg;
#pragma unroll
            for (int mi = 0; mi < 2; mi++) {
                int row = (wm << 5) + (mi << 4) + g;
                av[ks][mi][0] = f2tf32(Asf[row * PP_AS + col]);
                av[ks][mi][1] = f2tf32(Asf[(row + 8) * PP_AS + col]);
                av[ks][mi][2] = f2tf32(Asf[row * PP_AS + col + 4]);
                av[ks][mi][3] = f2tf32(Asf[(row + 8) * PP_AS + col + 4]);
            }
        }
        // kc stride in float4 units = 4 * WCHUNK_FLOATS / 4 = WCHUNK_FLOATS
        const float4* wc = wbase + (size_t)kc * WCHUNK_FLOATS;
#pragma unroll
        for (int par = 0; par < 2; par++) {
            float4 bq[5][2];
#pragma unroll
            for (int gate = 0; gate < 5; gate++) {
                int fo = bo4 + (gate << 8) + (par << 6);
                bq[gate][0] = __ldg(wc + fo);
                bq[gate][1] = __ldg(wc + fo + 1);
            }
#pragma unroll
            for (int gate = 0; gate < 5; gate++) {
                int f = gate * 2 + par;
#pragma unroll
                for (int mi = 0; mi < 2; mi++) {
                    mma_tf32(acc[mi][f], av[0][mi], __float_as_uint(bq[gate][0].x), __float_as_uint(bq[gate][0].y));
                    mma_tf32(acc[mi][f], av[1][mi], __float_as_uint(bq[gate][0].z), __float_as_uint(bq[gate][0].w));
                    mma_tf32(acc[mi][f], av[2][mi], __float_as_uint(bq[gate][1].x), __float_as_uint(bq[gate][1].y));
                    mma_tf32(acc[mi][f], av[3][mi], __float_as_uint(bq[gate][1].z), __float_as_uint(bq[gate][1].w));
                }
            }
        }
    }

    // store acc -> g_P0 (n = gate*128 + ht*32 + local)
#pragma unroll
    for (int mi = 0; mi < 2; mi++)
#pragma unroll
        for (int rs = 0; rs < 2; rs++) {
            int r1 = r0 + (wm << 5) + (mi << 4) + g + (rs << 3);
            int ci = rs << 1;
#pragma unroll
            for (int par = 0; par < 2; par++) {
                int nloc = ht * 32 + wn * 16 + par * 8 + (tg << 1);
#pragma unroll
                for (int gate = 0; gate < 5; gate++) {
                    int f = gate * 2 + par;
                    float2 v = make_float2(acc[mi][f][ci], acc[mi][f][ci + 1]);
                    *(float2*)(g_P0 + (size_t)(r1 * NB + j) * FIVEH + gate * 128 + nloc) = v;
                }
            }
        }
#undef PP_ISSUE
}

// =====================================================================
// MAIN wavefront kernel. CTA 128 thr (4 warps, 2Mx2N), tile M=64 x N=160.
// A via 3-stage cp.async (pre-rounded, no cvt). B via direct LDG.128 frags.
// Register-resident epilogue (no Z smem).
// =====================================================================
#define WF_AS 36
#define WF_A_FLOATS (64 * WF_AS)          // 2304
#define WF_SMEM (3 * WF_A_FLOATS * 4)     // 27648

__device__ void process_cell_tile(int t, int j, int l, int mtile, int htile,
                                  const float* __restrict__ bias,
                                  float* __restrict__ outh, float* __restrict__ outc,
                                  float* smem) {
    const int tid = threadIdx.x;
    const int warp = tid >> 5, lane = tid & 31;
    const int wm = warp >> 1, wn = warp & 1;
    const int g = lane >> 2, tg = lane & 3;
    const int b0 = mtile << 6;
    const int h0 = htile << 5;
    const int lj = l * NB + j;

    // A sources (all pre-rounded tf32, stride HH)
    const float* srcs[3];
    int nc, kc0;
    if (l == 0) {
        nc = 8; kc0 = 4;
        srcs[0] = (t == 0) ? g_rowh_r + ((0 * NB + j) * BB + b0) * HH
                           : g_h0 + (((t - 1) * NB + j) * BB + b0) * HH;
        srcs[1] = (j == 0) ? g_colh_r + b0 * HH
                           : g_h0 + ((t * NB + (j - 1)) * BB + b0) * HH;
        srcs[2] = srcs[1];
    } else {
        nc = 12; kc0 = 0;
        srcs[0] = g_h0 + ((t * NB + j) * BB + b0) * HH;
        srcs[1] = (t == 0) ? g_rowh_r + ((1 * NB + j) * BB + b0) * HH
                           : g_h1r + (((t - 1) * NB + j) * BB + b0) * HH;
        srcs[2] = (j == 0) ? g_colh_r + b0 * HH
                           : g_h1r + ((t * NB + (j - 1)) * BB + b0) * HH;
    }
    const float4* wbase = (const float4*)(g_Wfrag + ((size_t)(lj * 12 + kc0) * 4 + htile) * WCHUNK_FLOATS);
    const int bo4 = ((wn * 16 + g) << 3) + (tg << 1);

    float acc[2][10][4];
#pragma unroll
    for (int i = 0; i < 2; i++)
#pragma unroll
        for (int f = 0; f < 10; f++)
#pragma unroll
            for (int ci = 0; ci < 4; ci++) acc[i][f][ci] = 0.0f;

    __syncthreads();  // previous tile's A stages fully consumed

#define WF_ISSUE(chunk, stg)                                                       \
    {                                                                              \
        const float* asrc = srcs[(chunk) >> 2];                                    \
        int hoff = ((chunk) & 3) << 5;                                             \
        float* As = smem + (stg) * WF_A_FLOATS;                                    \
        _Pragma("unroll") for (int i = 0; i < 4; i++) {                            \
            int idx = tid + (i << 7);                                              \
            int r = idx >> 3;                                                      \
            int c4 = (idx & 7) << 2;                                               \
            cp16(As + r * WF_AS + c4, asrc + r * HH + hoff + c4);                  \
        }                                                                          \
    }

    WF_ISSUE(0, 0); cp_commit();
    WF_ISSUE(1, 1); cp_commit();

    for (int kc = 0; kc < nc; kc++) {
        cp_wait<1>();
        __syncthreads();
        int nxt = kc + 2;
        if (nxt < nc) { WF_ISSUE(nxt, nxt % 3); }
        cp_commit();

        const float* Asf = smem + (kc % 3) * WF_A_FLOATS;
        const unsigned* Asu = (const unsigned*)Asf;
        unsigned av[4][2][4];
#pragma unroll
        for (int ks = 0; ks < 4; ks++) {
            int col = (ks << 3) + tg;
#pragma unroll
            for (int mi = 0; mi < 2; mi++) {
                int row = (wm << 5) + (mi << 4) + g;
                av[ks][mi][0] = Asu[row * WF_AS + col];
                av[ks][mi][1] = Asu[(row + 8) * WF_AS + col];
                av[ks][mi][2] = Asu[row * WF_AS + col + 4];
                av[ks][mi][3] = Asu[(row + 8) * WF_AS + col + 4];
            }
        }
        // kc stride in float4 units = WCHUNK_FLOATS
        const float4* wc = wbase + (size_t)kc * WCHUNK_FLOATS;
#pragma unroll
        for (int par = 0; par < 2; par++) {
            float4 bq[5][2];
#pragma unroll
            for (int gate = 0; gate < 5; gate++) {
                int fo = bo4 + (gate << 8) + (par << 6);
                bq[gate][0] = __ldg(wc + fo);
                bq[gate][1] = __ldg(wc + fo + 1);
            }
#pragma unroll
            for (int gate = 0; gate < 5; gate++) {
                int f = gate * 2 + par;
#pragma unroll
                for (int mi = 0; mi < 2; mi++) {
                    mma_tf32(acc[mi][f], av[0][mi], __float_as_uint(bq[gate][0].x), __float_as_uint(bq[gate][0].y));
                    mma_tf32(acc[mi][f], av[1][mi], __float_as_uint(bq[gate][0].z), __float_as_uint(bq[gate][0].w));
                    mma_tf32(acc[mi][f], av[2][mi], __float_as_uint(bq[gate][1].x), __float_as_uint(bq[gate][1].y));
                    mma_tf32(acc[mi][f], av[3][mi], __float_as_uint(bq[gate][1].z), __float_as_uint(bq[gate][1].w));
                }
            }
        }
    }
#undef WF_ISSUE

    // ---- register epilogue ----
    const float* brow = bias + lj * FIVEH;
    const float* ctp; int cts;
    if (t == 0)      { ctp = g_rowc + (j * BB + b0) * HH; cts = HH; }
    else if (l == 0) { ctp = g_c0 + (((t - 1) * NB + j) * BB + b0) * HH; cts = HH; }
    else             { ctp = outc + ((b0 * TOUT + (t - 1)) * NB + j) * HH; cts = TOUT * NB * HH; }
    const float* csp; int css;
    if (j == 0)      { csp = g_colc + b0 * HH; css = HH; }
    else if (l == 0) { csp = g_c0 + ((t * NB + (j - 1)) * BB + b0) * HH; css = HH; }
    else             { csp = outc + ((b0 * TOUT + t) * NB + (j - 1)) * HH; css = TOUT * NB * HH; }

#pragma unroll
    for (int mi = 0; mi < 2; mi++)
#pragma unroll
        for (int rs = 0; rs < 2; rs++) {
            int m = (wm << 5) + (mi << 4) + g + (rs << 3);
            int ci = rs << 1;
            const float* ctr = ctp + m * cts;
            const float* csr = csp + m * css;
#pragma unroll
            for (int par = 0; par < 2; par++) {
                int ha = h0 + wn * 16 + par * 8 + (tg << 1);
                float z[5][2];
#pragma unroll
                for (int gate = 0; gate < 5; gate++) {
                    int f = gate * 2 + par;
                    z[gate][0] = acc[mi][f][ci];
                    z[gate][1] = acc[mi][f][ci + 1];
                }
                if (l == 0) {
                    const float* p0 = g_P0 + (size_t)(((b0 + m) * TOUT + t) * NB + j) * FIVEH;
#pragma unroll
                    for (int gate = 0; gate < 5; gate++) {
                        float2 pv = *(const float2*)(p0 + gate * 128 + ha);
                        z[gate][0] += pv.x; z[gate][1] += pv.y;
                    }
                }
#pragma unroll
                for (int gate = 0; gate < 5; gate++) {
                    float2 bv = *(const float2*)(brow + gate * 128 + ha);
                    z[gate][0] += bv.x; z[gate][1] += bv.y;
                }
                float2 ctv = *(const float2*)(ctr + ha);
                float2 csv = *(const float2*)(csr + ha);
                float cv0 = sigm(z[0][0]) * tanh_fast(z[4][0]) + sigm(z[2][0]) * ctv.x + sigm(z[1][0]) * csv.x;
                float cv1 = sigm(z[0][1]) * tanh_fast(z[4][1]) + sigm(z[2][1]) * ctv.y + sigm(z[1][1]) * csv.y;
                float hv0 = sigm(z[3][0]) * tanh_fast(cv0);
                float hv1 = sigm(z[3][1]) * tanh_fast(cv1);
                if (l == 0) {
                    size_t off = (size_t)((t * NB + j) * BB + b0 + m) * HH + ha;
                    *(float2*)(g_h0 + off) = make_float2(f2tf32f(hv0), f2tf32f(hv1));
                    *(float2*)(g_c0 + off) = make_float2(cv0, cv1);
                } else {
                    size_t oo = (size_t)(((b0 + m) * TOUT + t) * NB + j) * HH + ha;
                    *(float2*)(outh + oo) = make_float2(hv0, hv1);
                    *(float2*)(outc + oo) = make_float2(cv0, cv1);
                    size_t so = (size_t)((t * NB + j) * BB + b0 + m) * HH + ha;
                    *(float2*)(g_h1r + so) = make_float2(f2tf32f(hv0), f2tf32f(hv1));
                }
            }
        }
}

__global__ void __launch_bounds__(128, 2)
st_main(const float* __restrict__ bias, float* __restrict__ outh, float* __restrict__ outc) {
    extern __shared__ float smem[];
    unsigned long long gen = 0;
    for (int d = 0; d < TOUT + NB; d++) {  // 49 diagonals
        int lo0 = (d - (NB - 1) > 0) ? d - (NB - 1) : 0;
        int hi0 = (d < TOUT - 1) ? d : TOUT - 1;
        int n0 = hi0 - lo0 + 1;
        if (n0 < 0) n0 = 0;
        int e = d - 1;
        int lo1 = 0, n1 = 0;
        if (e >= 0) {
            lo1 = (e - (NB - 1) > 0) ? e - (NB - 1) : 0;
            int hi1 = (e < TOUT - 1) ? e : TOUT - 1;
            n1 = hi1 - lo1 + 1;
            if (n1 < 0) n1 = 0;
        }
        int items = (n0 + n1) << 4;  // 16 tiles/cell (4 mtiles x 4 htiles)
        for (int it = blockIdx.x; it < items; it += gridDim.x) {
            int cell = it >> 4;
            int l, t, jj;
            if (cell < n0) { l = 0; t = lo0 + cell; jj = d - t; }
            else           { l = 1; t = lo1 + (cell - n0); jj = e - t; }
            process_cell_tile(t, jj, l, (it >> 2) & 3, it & 3, bias, outh, outc, smem);
        }
        gen++;
        __syncthreads();
        if (threadIdx.x == 0) {
            __threadfence();
            atomicAdd(&g_bar, 1ULL);
            unsigned long long target = gen * (unsigned long long)gridDim.x;
            while (*(volatile unsigned long long*)&g_bar < target) __nanosleep(32);
            __threadfence();
        }
        __syncthreads();
    }
}

// ---------------- launch ----------------
extern "C" void kernel_launch(void* const* d_in, const int* in_sizes, int n_in,
                              void* d_out, int out_size) {
    const float* hs = (const float*)d_in[0];
    const float* cs = (const float*)d_in[1];
    const float* gts = (const float*)d_in[2];
    const float* p = (const float*)d_in[3];
    const float* U = (const float*)d_in[4];
    const float* Wt = (const float*)d_in[5];
    const float* Ws = (const float*)d_in[6];
    const float* b = (const float*)d_in[7];

    float* outh = (float*)d_out;
    float* outc = outh + (size_t)BB * TOUT * NB * HH;

    prep_wfrag<<<11520, 128>>>(U, Wt, Ws);
    prep_rows<<<(NB * BB * HH + 255) / 256, 256>>>(hs, cs, gts);
    prep_cols<<<(BB * HH + 255) / 256, 256>>>();

    cudaFuncSetAttribute(prepass, cudaFuncAttributeMaxDynamicSharedMemorySize, PP_SMEM);
    prepass<<<24 * 200, 256, PP_SMEM>>>(p);

    int dev = 0;
    cudaGetDevice(&dev);
    int nsm = 148;
    cudaDeviceGetAttribute(&nsm, cudaDevAttrMultiProcessorCount, dev);
    cudaFuncSetAttribute(st_main, cudaFuncAttributeMaxDynamicSharedMemorySize, WF_SMEM);
    int occ = 0;
    cudaOccupancyMaxActiveBlocksPerMultiprocessor(&occ, st_main, 128, WF_SMEM);
    if (occ < 1) occ = 1;
    if (occ > 2) occ = 2;
    st_main<<<nsm * occ, 128, WF_SMEM>>>(b, outh, outc);
}

// round 8
// speedup vs baseline: 2.2973x; 1.1157x over previous
#include <cuda_runtime.h>
#include <math.h>

#define BB 256
#define TIN 49
#define TOUT 25
#define NB 24
#define HH 128
#define FIVEH 640
#define KTOT 384

#define WCHUNK_FLOATS 5120  // one (lj,kc,ht) B chunk: 5 gates x 32 cols x 4 tg x 8 s
#define NPP (NB * 400)      // 9600 prepass items (per j: 100 r-tiles x 4 ht)

// ---------------- device scratch ----------------
__device__ float g_Wfrag[48 * 12 * 4 * WCHUNK_FLOATS];   // 45 MB fragment-major weights
__device__ float g_P0[BB * TOUT * NB * FIVEH];    // p @ U[0]
__device__ float g_h0[TOUT * NB * BB * HH];       // layer-0 h (tf32-rounded)
__device__ float g_c0[TOUT * NB * BB * HH];       // layer-0 c (full)
__device__ float g_h1r[TOUT * NB * BB * HH];      // layer-1 h rounded shadow
__device__ float g_rowh[2 * NB * BB * HH];
__device__ float g_rowh_r[2 * NB * BB * HH];
__device__ float g_rowc[NB * BB * HH];
__device__ float g_colh_r[BB * HH];
__device__ float g_colc[BB * HH];
// dataflow flags
__device__ int g_fP0[NB];                 // target 400
__device__ int g_fcell[2][TOUT][NB][4];   // [l][t][j][mt], target 4

// ---------------- helpers ----------------
__device__ __forceinline__ float sigm(float x) { return 1.0f / (1.0f + __expf(-x)); }
__device__ __forceinline__ float tanh_fast(float x) { return 2.0f / (1.0f + __expf(-2.0f * x)) - 1.0f; }

__device__ __forceinline__ unsigned f2tf32(float v) {
    unsigned u;
    asm("cvt.rna.tf32.f32 %0, %1;" : "=r"(u) : "f"(v));
    return u;
}
__device__ __forceinline__ float f2tf32f(float v) { return __uint_as_float(f2tf32(v)); }

__device__ __forceinline__ void mma_tf32(float* c, const unsigned* a, unsigned b0, unsigned b1) {
    asm volatile(
        "mma.sync.aligned.m16n8k8.row.col.f32.tf32.tf32.f32 "
        "{%0,%1,%2,%3}, {%4,%5,%6,%7}, {%8,%9}, {%0,%1,%2,%3};\n"
        : "+f"(c[0]), "+f"(c[1]), "+f"(c[2]), "+f"(c[3])
        : "r"(a[0]), "r"(a[1]), "r"(a[2]), "r"(a[3]), "r"(b0), "r"(b1));
}

__device__ __forceinline__ void cp16(float* dst_smem, const float* src_gmem) {
    unsigned d = (unsigned)__cvta_generic_to_shared(dst_smem);
    asm volatile("cp.async.cg.shared.global [%0], [%1], 16;\n" ::"r"(d), "l"(src_gmem));
}
__device__ __forceinline__ void cp_commit() { asm volatile("cp.async.commit_group;\n"); }
template <int N>
__device__ __forceinline__ void cp_wait() { asm volatile("cp.async.wait_group %0;\n" ::"n"(N)); }

// spin-wait on a device flag (tid0 only; caller must __syncthreads after all waits)
__device__ __forceinline__ void spin_flag(const int* f, int target) {
    while (*(volatile const int*)f < target) __nanosleep(40);
}

// ---------------- prep: fragment-major weight pack ----------------
__global__ void prep_wfrag(const float* __restrict__ U, const float* __restrict__ Wt,
                           const float* __restrict__ Ws) {
    __shared__ float tile[32][33];
    int bx = blockIdx.x;
    int gate = bx % 5;
    int ht = (bx / 5) & 3;
    int kc = (bx / 20) % 12;
    int lj = bx / 240;
    int tx = threadIdx.x & 31, ty = threadIdx.x >> 5;

    const float* src;
    int kbase;
    if (kc < 4) { src = U; kbase = kc * 32; }
    else if (kc < 8) { src = Wt; kbase = (kc - 4) * 32; }
    else { src = Ws; kbase = (kc - 8) * 32; }
    int n0 = gate * 128 + ht * 32;

    for (int kk = ty; kk < 32; kk += 4) {
        float v = src[((size_t)lj * HH + kbase + kk) * FIVEH + n0 + tx];
        tile[kk][tx] = f2tf32f(v);
    }
    __syncthreads();
    float* out = g_Wfrag + ((size_t)(lj * 12 + kc) * 4 + ht) * WCHUNK_FLOATS + gate * 1024;
    int q = tx;
    int kk = (q >> 3) + ((q & 7) << 2);  // tg = q>>3, s = q&7, k-row = tg + 4s
    for (int hh = ty; hh < 32; hh += 4) {
        out[hh * 32 + q] = tile[kk][hh];
    }
}

__global__ void zero_flags() {
    int i = blockIdx.x * blockDim.x + threadIdx.x;
    if (i < NB) g_fP0[i] = 0;
    if (i < 2 * TOUT * NB * 4) (&g_fcell[0][0][0][0])[i] = 0;
}

// ---------------- prep: row/col means ----------------
__global__ void prep_rows(const float* __restrict__ hs, const float* __restrict__ cs,
                          const float* __restrict__ gts) {
    int i = blockIdx.x * blockDim.x + threadIdx.x;
    const int total = NB * BB * HH;
    if (i >= total) return;
    int h = i % HH;
    int b = (i / HH) % BB;
    int j = i / (HH * BB);
    const float* ph = hs + (b * TIN * NB + j) * HH + h;
    const float* pc = cs + (b * TIN * NB + j) * HH + h;
    float sh = 0.f, sc = 0.f;
    for (int t = 0; t < TIN; t++) { sh += ph[t * NB * HH]; sc += pc[t * NB * HH]; }
    float gv = gts[(b * NB + j) * HH + h];
    float r0 = sh / 49.0f, r1 = (sh + gv) / 50.0f;
    int o0 = (0 * NB + j) * BB * HH + b * HH + h;
    int o1 = (1 * NB + j) * BB * HH + b * HH + h;
    g_rowh[o0] = r0; g_rowh[o1] = r1;
    g_rowh_r[o0] = f2tf32f(r0);
    g_rowh_r[o1] = f2tf32f(r1);
    g_rowc[j * BB * HH + b * HH + h] = sc / 49.0f;
}

__global__ void prep_cols() {
    int i = blockIdx.x * blockDim.x + threadIdx.x;
    if (i >= BB * HH) return;
    float sh = 0.f, sc = 0.f;
    for (int j = 0; j < NB; j++) {
        sh += g_rowh[j * BB * HH + i];
        sc += g_rowc[j * BB * HH + i];
    }
    g_colh_r[i] = f2tf32f(sh / (float)NB);
    g_colc[i] = sc / (float)NB;
}

// =====================================================================
// unified persistent kernel: prepass items + wavefront items, dataflow sync
// CTA 128 thr (4 warps, 2Mx2N), tile M=64 x N=160.
// =====================================================================
#define WF_AS 36
#define WF_A_FLOATS (64 * WF_AS)          // 2304
#define WF_SMEM (3 * WF_A_FLOATS * 4)     // 27648

__device__ __forceinline__ void issueA64(const float* __restrict__ asrc, int astr, int hoff,
                                         float* As) {
    const int tid = threadIdx.x;
#pragma unroll
    for (int i = 0; i < 4; i++) {
        int idx = tid + (i << 7);
        int r = idx >> 3;
        int c4 = (idx & 7) << 2;
        cp16(As + r * WF_AS + c4, asrc + r * astr + hoff + c4);
    }
}

// ---- prepass tile: P0[r0..r0+63][j][ht*32 block per gate] = p @ U0 ----
__device__ void pp_tile(int item, const float* __restrict__ p, float* smem) {
    int j = item / 400;
    int rem = item % 400;
    int r0 = (rem >> 2) << 6;
    int ht = rem & 3;

    const int tid = threadIdx.x;
    const int warp = tid >> 5, lane = tid & 31;
    const int wm = warp >> 1, wn = warp & 1;
    const int g = lane >> 2, tg = lane & 3;

    const float* asrc = p + (r0 * NB + j) * HH;
    const int astr = NB * HH;
    const float4* wbase = (const float4*)(g_Wfrag + ((size_t)(j * 12) * 4 + ht) * WCHUNK_FLOATS);
    const int bo4 = ((wn * 16 + g) << 3) + (tg << 1);

    float acc[2][10][4];
#pragma unroll
    for (int i = 0; i < 2; i++)
#pragma unroll
        for (int f = 0; f < 10; f++)
#pragma unroll
            for (int ci = 0; ci < 4; ci++) acc[i][f][ci] = 0.0f;

    __syncthreads();
    issueA64(asrc, astr, 0, smem); cp_commit();
    issueA64(asrc, astr, 32, smem + WF_A_FLOATS); cp_commit();

    for (int kc = 0; kc < 4; kc++) {
        cp_wait<1>();
        __syncthreads();
        int nxt = kc + 2;
        if (nxt < 4) issueA64(asrc, astr, nxt << 5, smem + (nxt % 3) * WF_A_FLOATS);
        cp_commit();

        const float* Asf = smem + (kc % 3) * WF_A_FLOATS;
        unsigned av[4][2][4];
#pragma unroll
        for (int ks = 0; ks < 4; ks++) {
            int col = (ks << 3) + tg;
#pragma unroll
            for (int mi = 0; mi < 2; mi++) {
                int row = (wm << 5) + (mi << 4) + g;
                av[ks][mi][0] = f2tf32(Asf[row * WF_AS + col]);
                av[ks][mi][1] = f2tf32(Asf[(row + 8) * WF_AS + col]);
                av[ks][mi][2] = f2tf32(Asf[row * WF_AS + col + 4]);
                av[ks][mi][3] = f2tf32(Asf[(row + 8) * WF_AS + col + 4]);
            }
        }
        const float4* wc = wbase + (size_t)kc * WCHUNK_FLOATS;
#pragma unroll
        for (int par = 0; par < 2; par++) {
            float4 bq[5][2];
#pragma unroll
            for (int gate = 0; gate < 5; gate++) {
                int fo = bo4 + (gate << 8) + (par << 6);
                bq[gate][0] = __ldg(wc + fo);
                bq[gate][1] = __ldg(wc + fo + 1);
            }
#pragma unroll
            for (int gate = 0; gate < 5; gate++) {
                int f = gate * 2 + par;
#pragma unroll
                for (int mi = 0; mi < 2; mi++) {
                    mma_tf32(acc[mi][f], av[0][mi], __float_as_uint(bq[gate][0].x), __float_as_uint(bq[gate][0].y));
                    mma_tf32(acc[mi][f], av[1][mi], __float_as_uint(bq[gate][0].z), __float_as_uint(bq[gate][0].w));
                    mma_tf32(acc[mi][f], av[2][mi], __float_as_uint(bq[gate][1].x), __float_as_uint(bq[gate][1].y));
                    mma_tf32(acc[mi][f], av[3][mi], __float_as_uint(bq[gate][1].z), __float_as_uint(bq[gate][1].w));
                }
            }
        }
    }

#pragma unroll
    for (int mi = 0; mi < 2; mi++)
#pragma unroll
        for (int rs = 0; rs < 2; rs++) {
            int r1 = r0 + (wm << 5) + (mi << 4) + g + (rs << 3);
            int ci = rs << 1;
#pragma unroll
            for (int par = 0; par < 2; par++) {
                int nloc = ht * 32 + wn * 16 + par * 8 + (tg << 1);
#pragma unroll
                for (int gate = 0; gate < 5; gate++) {
                    int f = gate * 2 + par;
                    *(float2*)(g_P0 + (size_t)(r1 * NB + j) * FIVEH + gate * 128 + nloc) =
                        make_float2(acc[mi][f][ci], acc[mi][f][ci + 1]);
                }
            }
        }

    __threadfence();
    __syncthreads();
    if (tid == 0) atomicAdd(&g_fP0[j], 1);
}

// ---- wavefront tile ----
__device__ void process_cell_tile(int t, int j, int l, int mtile, int htile,
                                  const float* __restrict__ bias,
                                  float* __restrict__ outh, float* __restrict__ outc,
                                  float* smem) {
    const int tid = threadIdx.x;
    const int warp = tid >> 5, lane = tid & 31;
    const int wm = warp >> 1, wn = warp & 1;
    const int g = lane >> 2, tg = lane & 3;
    const int b0 = mtile << 6;
    const int h0 = htile << 5;
    const int lj = l * NB + j;

    // ---- dataflow waits ----
    if (tid == 0) {
        if (l == 0) {
            if (t > 0) spin_flag(&g_fcell[0][t - 1][j][mtile], 4);
            if (j > 0) spin_flag(&g_fcell[0][t][j - 1][mtile], 4);
            spin_flag(&g_fP0[j], 400);
        } else {
            spin_flag(&g_fcell[0][t][j][mtile], 4);
            if (t > 0) spin_flag(&g_fcell[1][t - 1][j][mtile], 4);
            if (j > 0) spin_flag(&g_fcell[1][t][j - 1][mtile], 4);
        }
    }
    __syncthreads();  // also guards previous tile's smem stages

    const float* srcs[3];
    int nc, kc0;
    if (l == 0) {
        nc = 8; kc0 = 4;
        srcs[0] = (t == 0) ? g_rowh_r + ((0 * NB + j) * BB + b0) * HH
                           : g_h0 + (((t - 1) * NB + j) * BB + b0) * HH;
        srcs[1] = (j == 0) ? g_colh_r + b0 * HH
                           : g_h0 + ((t * NB + (j - 1)) * BB + b0) * HH;
        srcs[2] = srcs[1];
    } else {
        nc = 12; kc0 = 0;
        srcs[0] = g_h0 + ((t * NB + j) * BB + b0) * HH;
        srcs[1] = (t == 0) ? g_rowh_r + ((1 * NB + j) * BB + b0) * HH
                           : g_h1r + (((t - 1) * NB + j) * BB + b0) * HH;
        srcs[2] = (j == 0) ? g_colh_r + b0 * HH
                           : g_h1r + ((t * NB + (j - 1)) * BB + b0) * HH;
    }
    const float4* wbase = (const float4*)(g_Wfrag + ((size_t)(lj * 12 + kc0) * 4 + htile) * WCHUNK_FLOATS);
    const int bo4 = ((wn * 16 + g) << 3) + (tg << 1);

    float acc[2][10][4];
#pragma unroll
    for (int i = 0; i < 2; i++)
#pragma unroll
        for (int f = 0; f < 10; f++)
#pragma unroll
            for (int ci = 0; ci < 4; ci++) acc[i][f][ci] = 0.0f;

    issueA64(srcs[0], HH, 0, smem); cp_commit();
    issueA64(srcs[0], HH, 32, smem + WF_A_FLOATS); cp_commit();

    for (int kc = 0; kc < nc; kc++) {
        cp_wait<1>();
        __syncthreads();
        int nxt = kc + 2;
        if (nxt < nc) issueA64(srcs[nxt >> 2], HH, (nxt & 3) << 5, smem + (nxt % 3) * WF_A_FLOATS);
        cp_commit();

        const unsigned* Asu = (const unsigned*)(smem + (kc % 3) * WF_A_FLOATS);
        unsigned av[4][2][4];
#pragma unroll
        for (int ks = 0; ks < 4; ks++) {
            int col = (ks << 3) + tg;
#pragma unroll
            for (int mi = 0; mi < 2; mi++) {
                int row = (wm << 5) + (mi << 4) + g;
                av[ks][mi][0] = Asu[row * WF_AS + col];
                av[ks][mi][1] = Asu[(row + 8) * WF_AS + col];
                av[ks][mi][2] = Asu[row * WF_AS + col + 4];
                av[ks][mi][3] = Asu[(row + 8) * WF_AS + col + 4];
            }
        }
        const float4* wc = wbase + (size_t)kc * WCHUNK_FLOATS;
#pragma unroll
        for (int par = 0; par < 2; par++) {
            float4 bq[5][2];
#pragma unroll
            for (int gate = 0; gate < 5; gate++) {
                int fo = bo4 + (gate << 8) + (par << 6);
                bq[gate][0] = __ldg(wc + fo);
                bq[gate][1] = __ldg(wc + fo + 1);
            }
#pragma unroll
            for (int gate = 0; gate < 5; gate++) {
                int f = gate * 2 + par;
#pragma unroll
                for (int mi = 0; mi < 2; mi++) {
                    mma_tf32(acc[mi][f], av[0][mi], __float_as_uint(bq[gate][0].x), __float_as_uint(bq[gate][0].y));
                    mma_tf32(acc[mi][f], av[1][mi], __float_as_uint(bq[gate][0].z), __float_as_uint(bq[gate][0].w));
                    mma_tf32(acc[mi][f], av[2][mi], __float_as_uint(bq[gate][1].x), __float_as_uint(bq[gate][1].y));
                    mma_tf32(acc[mi][f], av[3][mi], __float_as_uint(bq[gate][1].z), __float_as_uint(bq[gate][1].w));
                }
            }
        }
    }

    // ---- register epilogue ----
    const float* brow = bias + lj * FIVEH;
    const float* ctp; int cts;
    if (t == 0)      { ctp = g_rowc + (j * BB + b0) * HH; cts = HH; }
    else if (l == 0) { ctp = g_c0 + (((t - 1) * NB + j) * BB + b0) * HH; cts = HH; }
    else             { ctp = outc + ((b0 * TOUT + (t - 1)) * NB + j) * HH; cts = TOUT * NB * HH; }
    const float* csp; int css;
    if (j == 0)      { csp = g_colc + b0 * HH; css = HH; }
    else if (l == 0) { csp = g_c0 + ((t * NB + (j - 1)) * BB + b0) * HH; css = HH; }
    else             { csp = outc + ((b0 * TOUT + t) * NB + (j - 1)) * HH; css = TOUT * NB * HH; }

#pragma unroll
    for (int mi = 0; mi < 2; mi++)
#pragma unroll
        for (int rs = 0; rs < 2; rs++) {
            int m = (wm << 5) + (mi << 4) + g + (rs << 3);
            int ci = rs << 1;
            const float* ctr = ctp + m * cts;
            const float* csr = csp + m * css;
#pragma unroll
            for (int par = 0; par < 2; par++) {
                int ha = h0 + wn * 16 + par * 8 + (tg << 1);
                float z[5][2];
#pragma unroll
                for (int gate = 0; gate < 5; gate++) {
                    int f = gate * 2 + par;
                    z[gate][0] = acc[mi][f][ci];
                    z[gate][1] = acc[mi][f][ci + 1];
                }
                if (l == 0) {
                    const float* p0 = g_P0 + (size_t)(((b0 + m) * TOUT + t) * NB + j) * FIVEH;
#pragma unroll
                    for (int gate = 0; gate < 5; gate++) {
                        float2 pv = *(const float2*)(p0 + gate * 128 + ha);
                        z[gate][0] += pv.x; z[gate][1] += pv.y;
                    }
                }
#pragma unroll
                for (int gate = 0; gate < 5; gate++) {
                    float2 bv = *(const float2*)(brow + gate * 128 + ha);
                    z[gate][0] += bv.x; z[gate][1] += bv.y;
                }
                float2 ctv = *(const float2*)(ctr + ha);
                float2 csv = *(const float2*)(csr + ha);
                float cv0 = sigm(z[0][0]) * tanh_fast(z[4][0]) + sigm(z[2][0]) * ctv.x + sigm(z[1][0]) * csv.x;
                float cv1 = sigm(z[0][1]) * tanh_fast(z[4][1]) + sigm(z[2][1]) * ctv.y + sigm(z[1][1]) * csv.y;
                float hv0 = sigm(z[3][0]) * tanh_fast(cv0);
                float hv1 = sigm(z[3][1]) * tanh_fast(cv1);
                if (l == 0) {
                    size_t off = (size_t)((t * NB + j) * BB + b0 + m) * HH + ha;
                    *(float2*)(g_h0 + off) = make_float2(f2tf32f(hv0), f2tf32f(hv1));
                    *(float2*)(g_c0 + off) = make_float2(cv0, cv1);
                } else {
                    size_t oo = (size_t)(((b0 + m) * TOUT + t) * NB + j) * HH + ha;
                    *(float2*)(outh + oo) = make_float2(hv0, hv1);
                    *(float2*)(outc + oo) = make_float2(cv0, cv1);
                    size_t so = (size_t)((t * NB + j) * BB + b0 + m) * HH + ha;
                    *(float2*)(g_h1r + so) = make_float2(f2tf32f(hv0), f2tf32f(hv1));
                }
            }
        }

    // ---- signal ----
    __threadfence();
    __syncthreads();
    if (tid == 0) atomicAdd(&g_fcell[l][t][j][mtile], 1);
}

__global__ void __launch_bounds__(128, 2)
st_main(const float* __restrict__ p, const float* __restrict__ bias,
        float* __restrict__ outh, float* __restrict__ outc) {
    extern __shared__ float smem[];
    const int G = gridDim.x, blk = blockIdx.x;

    // phase 1 (list head): prepass items, no deps
    for (int i = blk; i < NPP; i += G) pp_tile(i, p, smem);

    // phase 2: wavefront items in diagonal order, cyclic assignment continues
    int off = NPP % G;
    for (int d = 0; d < TOUT + NB; d++) {
        int lo0 = (d - (NB - 1) > 0) ? d - (NB - 1) : 0;
        int hi0 = (d < TOUT - 1) ? d : TOUT - 1;
        int n0 = hi0 - lo0 + 1;
        if (n0 < 0) n0 = 0;
        int e = d - 1;
        int lo1 = 0, n1 = 0;
        if (e >= 0) {
            lo1 = (e - (NB - 1) > 0) ? e - (NB - 1) : 0;
            int hi1 = (e < TOUT - 1) ? e : TOUT - 1;
            n1 = hi1 - lo1 + 1;
            if (n1 < 0) n1 = 0;
        }
        int items = (n0 + n1) << 4;
        int A = blk - off; if (A < 0) A += G;
        for (int it = A; it < items; it += G) {
            int cell = it >> 4;
            int l, t, jj;
            if (cell < n0) { l = 0; t = lo0 + cell; jj = d - t; }
            else           { l = 1; t = lo1 + (cell - n0); jj = e - t; }
            process_cell_tile(t, jj, l, (it >> 2) & 3, it & 3, bias, outh, outc, smem);
        }
        off = (off + items) % G;
    }
}

// ---------------- launch ----------------
extern "C" void kernel_launch(void* const* d_in, const int* in_sizes, int n_in,
                              void* d_out, int out_size) {
    const float* hs = (const float*)d_in[0];
    const float* cs = (const float*)d_in[1];
    const float* gts = (const float*)d_in[2];
    const float* p = (const float*)d_in[3];
    const float* U = (const float*)d_in[4];
    const float* Wt = (const float*)d_in[5];
    const float* Ws = (const float*)d_in[6];
    const float* b = (const float*)d_in[7];

    float* outh = (float*)d_out;
    float* outc = outh + (size_t)BB * TOUT * NB * HH;

    prep_wfrag<<<11520, 128>>>(U, Wt, Ws);
    zero_flags<<<(2 * TOUT * NB * 4 + 255) / 256, 256>>>();
    prep_rows<<<(NB * BB * HH + 255) / 256, 256>>>(hs, cs, gts);
    prep_cols<<<(BB * HH + 255) / 256, 256>>>();

    int dev = 0;
    cudaGetDevice(&dev);
    int nsm = 148;
    cudaDeviceGetAttribute(&nsm, cudaDevAttrMultiProcessorCount, dev);
    cudaFuncSetAttribute(st_main, cudaFuncAttributeMaxDynamicSharedMemorySize, WF_SMEM);
    int occ = 0;
    cudaOccupancyMaxActiveBlocksPerMultiprocessor(&occ, st_main, 128, WF_SMEM);
    if (occ < 1) occ = 1;
    if (occ > 2) occ = 2;
    st_main<<<nsm * occ, 128, WF_SMEM>>>(p, b, outh, outc);
}